// round 1
// baseline (speedup 1.0000x reference)
#include <cuda_runtime.h>
#include <math.h>

#define B_  16
#define D_  96
#define T_  512
#define H_  1024
#define BD_ (B_*D_)
#define TT_ 128

// ---- scratch (no allocs allowed) ----
__device__ float g_s[BD_];
__device__ float g_A[B_*D_*D_];
__device__ float g_x1[BD_*T_];
__device__ float g_x2[BD_*T_];
__device__ float g_h[BD_*H_];
__device__ float g_y[BD_*T_];
__device__ float g_bnmean[D_];
__device__ float g_bnrs[D_];

__device__ __forceinline__ float warp_sum(float v){
    #pragma unroll
    for(int o=16;o>0;o>>=1) v += __shfl_xor_sync(0xffffffffu, v, o);
    return v;
}
__device__ __forceinline__ float warp_max(float v){
    #pragma unroll
    for(int o=16;o>0;o>>=1) v = fmaxf(v, __shfl_xor_sync(0xffffffffu, v, o));
    return v;
}

// K1: s[row] = sum_t residual[row, t]
__global__ void k_sums(const float* __restrict__ res){
    int row = blockIdx.x;
    float v = 0.f;
    for (int t = threadIdx.x; t < T_; t += 128) v += res[row*T_ + t];
    v = warp_sum(v);
    __shared__ float red[4];
    int w = threadIdx.x >> 5;
    if ((threadIdx.x & 31) == 0) red[w] = v;
    __syncthreads();
    if (threadIdx.x == 0) g_s[row] = red[0]+red[1]+red[2]+red[3];
}

// K2: A[b,i,:] = softmax_j( s_i * s_j / T^1.5 )
__global__ void k_softmax(){
    int b = blockIdx.x / D_;
    int i = blockIdx.x % D_;
    int j = threadIdx.x;                    // 128 threads, 96 active
    const float SCALE = 1.0f/11585.237502960395f;   // 1/512^1.5
    float si = g_s[b*D_ + i];
    float z = (j < D_) ? si * g_s[b*D_ + j] * SCALE : -INFINITY;
    __shared__ float red[4];
    int w = threadIdx.x >> 5;
    float m = warp_max(z);
    if ((threadIdx.x & 31) == 0) red[w] = m;
    __syncthreads();
    m = fmaxf(fmaxf(red[0],red[1]), fmaxf(red[2],red[3]));
    float e = (j < D_) ? expf(z - m) : 0.f;
    float s = warp_sum(e);
    __syncthreads();
    if ((threadIdx.x & 31) == 0) red[w] = s;
    __syncthreads();
    s = red[0]+red[1]+red[2]+red[3];
    if (j < D_) g_A[(b*D_+i)*D_ + j] = e / s;
}

// K3: x1[b,d,t] = sum_e A[b,d,e]*res[b,e,t] + res[b,d,t]
__global__ void k_attn(const float* __restrict__ res){
    extern __shared__ float sm[];
    float* sA = sm;               // D_*D_
    float* sX = sm + D_*D_;       // D_*TT_
    int b  = blockIdx.y;
    int t0 = blockIdx.x * TT_;
    for (int i = threadIdx.x; i < D_*D_; i += 256) sA[i] = g_A[b*D_*D_ + i];
    for (int i = threadIdx.x; i < D_*TT_; i += 256){
        int d = i / TT_, t = i % TT_;
        sX[i] = res[(b*D_+d)*T_ + t0 + t];
    }
    __syncthreads();
    int t  = threadIdx.x & (TT_-1);
    int d0 = threadIdx.x / TT_;   // 0 or 1
    for (int d = d0; d < D_; d += 2){
        const float* ar = sA + d*D_;
        float acc = sX[d*TT_ + t];     // + residual
        #pragma unroll 16
        for (int e = 0; e < D_; e++) acc = fmaf(ar[e], sX[e*TT_ + t], acc);
        g_x1[(b*D_+d)*T_ + t0 + t] = acc;
    }
}

// K4a: BN stats per channel d over (B,T)
__global__ void k_bnstats(){
    int d = blockIdx.x;
    float s = 0.f, ss = 0.f;
    for (int i = threadIdx.x; i < B_*T_; i += 256){
        int b = i / T_, t = i % T_;
        float v = g_x1[(b*D_+d)*T_ + t];
        s += v; ss += v*v;
    }
    s = warp_sum(s); ss = warp_sum(ss);
    __shared__ float r1[8], r2[8];
    int w = threadIdx.x >> 5;
    if ((threadIdx.x & 31) == 0){ r1[w] = s; r2[w] = ss; }
    __syncthreads();
    if (threadIdx.x == 0){
        float S = 0.f, SS = 0.f;
        #pragma unroll
        for (int k = 0; k < 8; k++){ S += r1[k]; SS += r2[k]; }
        float mean = S / (float)(B_*T_);
        float var  = SS / (float)(B_*T_) - mean*mean;
        g_bnmean[d] = mean;
        g_bnrs[d]   = rsqrtf(var + 1e-5f);
    }
}

// K4b: x2 = (x1 - mu)*rs*gamma + beta
__global__ void k_bnapply(const float* __restrict__ gamma, const float* __restrict__ beta){
    int row = blockIdx.x;
    int d = row % D_;
    float m = g_bnmean[d], rs = g_bnrs[d];
    float ga = gamma[d], be = beta[d];
    for (int t = threadIdx.x; t < T_; t += 256)
        g_x2[row*T_ + t] = (g_x1[row*T_ + t] - m) * rs * ga + be;
}

// GEMM: C = act(A @ Bw + bias [+ Res]); 64x64 tile, BK=16, 256 thr, 4x4 micro
template<bool GELU_ACT>
__global__ void k_gemm(const float* __restrict__ A, const float* __restrict__ Bw,
                       const float* __restrict__ bias, const float* __restrict__ Res,
                       float* __restrict__ C, int M, int N, int K){
    __shared__ float As[16][68];
    __shared__ float Bs[16][68];
    int tid = threadIdx.x;
    int tx = tid & 15;
    int ty = tid >> 4;
    int bn = blockIdx.x * 64;
    int bm = blockIdx.y * 64;
    float acc[4][4] = {};
    for (int k0 = 0; k0 < K; k0 += 16){
        #pragma unroll
        for (int i = 0; i < 4; i++){
            int idx = tid + i*256;
            int r = idx >> 4, c = idx & 15;
            As[c][r] = A[(bm + r)*K + k0 + c];
        }
        #pragma unroll
        for (int i = 0; i < 4; i++){
            int idx = tid + i*256;
            int r = idx >> 6, c = idx & 63;
            Bs[r][c] = Bw[(k0 + r)*N + bn + c];
        }
        __syncthreads();
        #pragma unroll
        for (int kk = 0; kk < 16; kk++){
            float4 av = *(const float4*)&As[kk][ty*4];
            float4 bv = *(const float4*)&Bs[kk][tx*4];
            float a_[4] = {av.x, av.y, av.z, av.w};
            float b_[4] = {bv.x, bv.y, bv.z, bv.w};
            #pragma unroll
            for (int i = 0; i < 4; i++)
                #pragma unroll
                for (int j = 0; j < 4; j++)
                    acc[i][j] = fmaf(a_[i], b_[j], acc[i][j]);
        }
        __syncthreads();
    }
    #pragma unroll
    for (int i = 0; i < 4; i++){
        int row = bm + ty*4 + i;
        #pragma unroll
        for (int j = 0; j < 4; j++){
            int col = bn + tx*4 + j;
            float v = acc[i][j] + bias[col];
            if (GELU_ACT) v = 0.5f*v*(1.0f + erff(v*0.7071067811865476f));
            else          v += Res[row*N + col];
            C[row*N + col] = v;
        }
    }
}

// K7: LayerNorm over T, write final output
__global__ void k_ln(const float* __restrict__ lng, const float* __restrict__ lnb,
                     float* __restrict__ out){
    int row = blockIdx.x;
    const float* y = g_y + row*T_;
    int tid = threadIdx.x;
    float a = y[tid], b = y[tid + 256];
    __shared__ float red[8];
    int w = tid >> 5;
    float s = warp_sum(a + b);
    if ((tid & 31) == 0) red[w] = s;
    __syncthreads();
    float S = 0.f;
    #pragma unroll
    for (int k = 0; k < 8; k++) S += red[k];
    float mean = S * (1.f/512.f);
    float d0 = a - mean, d1 = b - mean;
    __syncthreads();
    float ss = warp_sum(d0*d0 + d1*d1);
    if ((tid & 31) == 0) red[w] = ss;
    __syncthreads();
    float SS = 0.f;
    #pragma unroll
    for (int k = 0; k < 8; k++) SS += red[k];
    float rs = rsqrtf(SS * (1.f/512.f) + 1e-5f);
    out[row*T_ + tid]       = d0*rs*lng[tid]       + lnb[tid];
    out[row*T_ + tid + 256] = d1*rs*lng[tid + 256] + lnb[tid + 256];
}

extern "C" void kernel_launch(void* const* d_in, const int* in_sizes, int n_in,
                              void* d_out, int out_size){
    const float* residual = (const float*)d_in[0];
    const float* bn_g = (const float*)d_in[1];
    const float* bn_b = (const float*)d_in[2];
    const float* ln_g = (const float*)d_in[3];
    const float* ln_b = (const float*)d_in[4];
    const float* W1   = (const float*)d_in[5];
    const float* b1   = (const float*)d_in[6];
    const float* W2   = (const float*)d_in[7];
    const float* b2   = (const float*)d_in[8];
    float* out = (float*)d_out;

    const int attn_smem = (D_*D_ + D_*TT_) * (int)sizeof(float);   // 86016 B
    cudaFuncSetAttribute(k_attn, cudaFuncAttributeMaxDynamicSharedMemorySize, attn_smem);

    float *px2, *ph, *py;
    cudaGetSymbolAddress((void**)&px2, g_x2);
    cudaGetSymbolAddress((void**)&ph,  g_h);
    cudaGetSymbolAddress((void**)&py,  g_y);

    k_sums<<<BD_, 128>>>(residual);
    k_softmax<<<BD_, 128>>>();
    dim3 ga(T_/TT_, B_);
    k_attn<<<ga, 256, attn_smem>>>(residual);
    k_bnstats<<<D_, 256>>>();
    k_bnapply<<<BD_, 256>>>(bn_g, bn_b);

    dim3 g1(H_/64, BD_/64);
    k_gemm<true ><<<g1, 256>>>(px2, W1, b1, nullptr, ph, BD_, H_, T_);
    dim3 g2(T_/64, BD_/64);
    k_gemm<false><<<g2, 256>>>(ph,  W2, b2, px2,    py, BD_, T_, H_);

    k_ln<<<BD_, 256>>>(ln_g, ln_b, out);
}

// round 2
// speedup vs baseline: 1.1402x; 1.1402x over previous
#include <cuda_runtime.h>
#include <math.h>

#define B_  16
#define D_  96
#define T_  512
#define H_  1024
#define BD_ (B_*D_)
#define TT_ 128

// ---- scratch ----
__device__ float g_A[B_*D_*D_];
__device__ float g_x1[BD_*T_];
__device__ float g_h[BD_*H_];
__device__ float g_y[BD_*T_];
__device__ float g_bnscale[D_];
__device__ float g_bnoff[D_];

__device__ __forceinline__ float warp_sum(float v){
    #pragma unroll
    for(int o=16;o>0;o>>=1) v += __shfl_xor_sync(0xffffffffu, v, o);
    return v;
}
__device__ __forceinline__ float warp_max(float v){
    #pragma unroll
    for(int o=16;o>0;o>>=1) v = fmaxf(v, __shfl_xor_sync(0xffffffffu, v, o));
    return v;
}

// K1: fused row-sums + rank-1 softmax. grid=B_, block=1024
__global__ void k_corr(const float* __restrict__ res){
    int b = blockIdx.x;
    int tid = threadIdx.x, w = tid >> 5, lane = tid & 31;
    __shared__ float s[D_];
    for (int r = w; r < D_; r += 32){
        const float4* p = (const float4*)(res + (b*D_ + r)*T_);
        float v = 0.f;
        #pragma unroll
        for (int t = lane; t < T_/4; t += 32){
            float4 q = p[t];
            v += (q.x + q.y) + (q.z + q.w);
        }
        v = warp_sum(v);
        if (lane == 0) s[r] = v;
    }
    __syncthreads();
    const float SCALE = 1.0f/11585.237502960395f;   // 1/512^1.5
    for (int r = w; r < D_; r += 32){
        float si = s[r];
        float z0 = si * s[lane     ] * SCALE;
        float z1 = si * s[lane + 32] * SCALE;
        float z2 = si * s[lane + 64] * SCALE;
        float m = warp_max(fmaxf(z0, fmaxf(z1, z2)));
        float e0 = expf(z0 - m), e1 = expf(z1 - m), e2 = expf(z2 - m);
        float inv = 1.f / warp_sum(e0 + e1 + e2);
        float* o = g_A + (b*D_ + r)*D_;
        o[lane]      = e0 * inv;
        o[lane + 32] = e1 * inv;
        o[lane + 64] = e2 * inv;
    }
}

// K2: x1[b,d,t] = sum_e A[b,d,e]*res[b,e,t] + res[b,d,t]
__global__ void k_attn(const float* __restrict__ res){
    extern __shared__ float sm[];
    float* sA = sm;               // D_*D_
    float* sX = sm + D_*D_;       // D_*TT_
    int b  = blockIdx.y;
    int t0 = blockIdx.x * TT_;
    for (int i = threadIdx.x; i < D_*D_; i += 512) sA[i] = g_A[b*D_*D_ + i];
    for (int i = threadIdx.x; i < D_*TT_; i += 512){
        int d = i / TT_, t = i % TT_;
        sX[i] = res[(b*D_+d)*T_ + t0 + t];
    }
    __syncthreads();
    int t  = threadIdx.x & (TT_-1);
    int d0 = threadIdx.x >> 7;    // 0..3
    for (int d = d0; d < D_; d += 4){
        const float* ar = sA + d*D_;
        float acc = sX[d*TT_ + t];     // + residual
        #pragma unroll 16
        for (int e = 0; e < D_; e++) acc = fmaf(ar[e], sX[e*TT_ + t], acc);
        g_x1[(b*D_+d)*T_ + t0 + t] = acc;
    }
}

// K3: BN stats per channel d over (B,T) -> fused scale/offset
__global__ void k_bnstats(const float* __restrict__ gamma, const float* __restrict__ beta){
    int d = blockIdx.x;
    int tid = threadIdx.x;
    float s = 0.f, ss = 0.f;
    for (int i = tid; i < B_*T_/4; i += 512){
        int b = i >> 7, t4 = i & 127;
        float4 v = *(const float4*)&g_x1[(b*D_+d)*T_ + t4*4];
        s  += (v.x + v.y) + (v.z + v.w);
        ss += (v.x*v.x + v.y*v.y) + (v.z*v.z + v.w*v.w);
    }
    s = warp_sum(s); ss = warp_sum(ss);
    __shared__ float r1[16], r2[16];
    int w = tid >> 5;
    if ((tid & 31) == 0){ r1[w] = s; r2[w] = ss; }
    __syncthreads();
    if (tid == 0){
        float S = 0.f, SS = 0.f;
        #pragma unroll
        for (int k = 0; k < 16; k++){ S += r1[k]; SS += r2[k]; }
        const float invN = 1.f/(float)(B_*T_);
        float mean = S * invN;
        float var  = SS * invN - mean*mean;
        float rs = rsqrtf(var + 1e-5f);
        float sc = rs * gamma[d];
        g_bnscale[d] = sc;
        g_bnoff[d]   = beta[d] - mean * sc;
    }
}

// GEMM: C = act(A' @ Bw + bias [+ BN(x1) residual])
// A' = BN(A) if BN_A. Tiles: 128 x (TN*16), BK=16, 256 thr, 8xTN micro, double-buffered.
template<int TN, bool GELU, bool BN_A, bool RES_BN>
__global__ void __launch_bounds__(256, 2) k_gemm(
    const float* __restrict__ A, const float* __restrict__ Bw,
    const float* __restrict__ bias, const float* __restrict__ ResX,
    float* __restrict__ C, int M, int N, int K)
{
    const int BN = TN * 16;
    const int NB4 = BN / 64;                 // B float4 loads per thread (2 or 1)
    __shared__ float As[2][16][128+4];
    __shared__ float Bs[2][16][BN+4];
    int tid = threadIdx.x;
    int tx = tid & 15, ty = tid >> 4;
    int bn = blockIdx.x * BN;
    int bm = blockIdx.y * 128;

    int aRow[2], aCol[2];
    float aSc[2], aOf[2];
    #pragma unroll
    for (int i = 0; i < 2; i++){
        int idx = tid + i*256;
        aRow[i] = idx >> 2; aCol[i] = (idx & 3) * 4;
        if (BN_A){
            int d = (bm + aRow[i]) % D_;
            aSc[i] = g_bnscale[d]; aOf[i] = g_bnoff[d];
        }
    }
    int bRow[NB4], bCol[NB4];
    #pragma unroll
    for (int i = 0; i < NB4; i++){
        int idx = tid + i*256;
        bRow[i] = idx / (BN/4); bCol[i] = (idx % (BN/4)) * 4;
    }

    float acc[8][TN];
    #pragma unroll
    for (int i = 0; i < 8; i++)
        #pragma unroll
        for (int j = 0; j < TN; j++) acc[i][j] = 0.f;

    const int KT = K / 16;

    // prologue: tile 0 -> buf 0
    #pragma unroll
    for (int i = 0; i < 2; i++){
        float4 v = *(const float4*)&A[(bm + aRow[i])*K + aCol[i]];
        if (BN_A){
            v.x = fmaf(v.x, aSc[i], aOf[i]); v.y = fmaf(v.y, aSc[i], aOf[i]);
            v.z = fmaf(v.z, aSc[i], aOf[i]); v.w = fmaf(v.w, aSc[i], aOf[i]);
        }
        As[0][aCol[i]+0][aRow[i]] = v.x;
        As[0][aCol[i]+1][aRow[i]] = v.y;
        As[0][aCol[i]+2][aRow[i]] = v.z;
        As[0][aCol[i]+3][aRow[i]] = v.w;
    }
    #pragma unroll
    for (int i = 0; i < NB4; i++)
        *(float4*)&Bs[0][bRow[i]][bCol[i]] = *(const float4*)&Bw[bRow[i]*N + bn + bCol[i]];
    __syncthreads();

    for (int kt = 0; kt < KT; kt++){
        int cur = kt & 1;
        float4 pa[2], pb[NB4];
        bool pf = (kt + 1 < KT);
        if (pf){
            #pragma unroll
            for (int i = 0; i < 2; i++)
                pa[i] = *(const float4*)&A[(bm + aRow[i])*K + (kt+1)*16 + aCol[i]];
            #pragma unroll
            for (int i = 0; i < NB4; i++)
                pb[i] = *(const float4*)&Bw[(bRow[i] + (kt+1)*16)*N + bn + bCol[i]];
        }
        #pragma unroll
        for (int kk = 0; kk < 16; kk++){
            float a[8], bf[TN];
            *(float4*)&a[0] = *(const float4*)&As[cur][kk][ty*8];
            *(float4*)&a[4] = *(const float4*)&As[cur][kk][ty*8 + 4];
            #pragma unroll
            for (int j = 0; j < TN; j += 4)
                *(float4*)&bf[j] = *(const float4*)&Bs[cur][kk][tx*TN + j];
            #pragma unroll
            for (int i = 0; i < 8; i++)
                #pragma unroll
                for (int j = 0; j < TN; j++)
                    acc[i][j] = fmaf(a[i], bf[j], acc[i][j]);
        }
        if (pf){
            int nxt = cur ^ 1;
            #pragma unroll
            for (int i = 0; i < 2; i++){
                float4 v = pa[i];
                if (BN_A){
                    v.x = fmaf(v.x, aSc[i], aOf[i]); v.y = fmaf(v.y, aSc[i], aOf[i]);
                    v.z = fmaf(v.z, aSc[i], aOf[i]); v.w = fmaf(v.w, aSc[i], aOf[i]);
                }
                As[nxt][aCol[i]+0][aRow[i]] = v.x;
                As[nxt][aCol[i]+1][aRow[i]] = v.y;
                As[nxt][aCol[i]+2][aRow[i]] = v.z;
                As[nxt][aCol[i]+3][aRow[i]] = v.w;
            }
            #pragma unroll
            for (int i = 0; i < NB4; i++)
                *(float4*)&Bs[nxt][bRow[i]][bCol[i]] = pb[i];
            __syncthreads();
        }
    }

    #pragma unroll
    for (int i = 0; i < 8; i++){
        int row = bm + ty*8 + i;
        float sc = 0.f, of = 0.f;
        if (RES_BN){ int d = row % D_; sc = g_bnscale[d]; of = g_bnoff[d]; }
        #pragma unroll
        for (int j = 0; j < TN; j += 4){
            int col = bn + tx*TN + j;
            float4 bb = *(const float4*)&bias[col];
            float4 v;
            v.x = acc[i][j+0] + bb.x; v.y = acc[i][j+1] + bb.y;
            v.z = acc[i][j+2] + bb.z; v.w = acc[i][j+3] + bb.w;
            if (GELU){
                v.x = 0.5f*v.x*(1.0f + erff(v.x*0.7071067811865476f));
                v.y = 0.5f*v.y*(1.0f + erff(v.y*0.7071067811865476f));
                v.z = 0.5f*v.z*(1.0f + erff(v.z*0.7071067811865476f));
                v.w = 0.5f*v.w*(1.0f + erff(v.w*0.7071067811865476f));
            }
            if (RES_BN){
                float4 r = *(const float4*)&ResX[row*N + col];
                v.x += fmaf(r.x, sc, of); v.y += fmaf(r.y, sc, of);
                v.z += fmaf(r.z, sc, of); v.w += fmaf(r.w, sc, of);
            }
            *(float4*)&C[row*N + col] = v;
        }
    }
}

// K6: LayerNorm over T, write final output
__global__ void k_ln(const float* __restrict__ lng, const float* __restrict__ lnb,
                     float* __restrict__ out){
    int row = blockIdx.x;
    const float* y = g_y + row*T_;
    int tid = threadIdx.x;
    float a = y[tid], b = y[tid + 256];
    __shared__ float red[8];
    int w = tid >> 5;
    float s = warp_sum(a + b);
    if ((tid & 31) == 0) red[w] = s;
    __syncthreads();
    float S = 0.f;
    #pragma unroll
    for (int k = 0; k < 8; k++) S += red[k];
    float mean = S * (1.f/512.f);
    float d0 = a - mean, d1 = b - mean;
    __syncthreads();
    float ss = warp_sum(d0*d0 + d1*d1);
    if ((tid & 31) == 0) red[w] = ss;
    __syncthreads();
    float SS = 0.f;
    #pragma unroll
    for (int k = 0; k < 8; k++) SS += red[k];
    float rs = rsqrtf(SS * (1.f/512.f) + 1e-5f);
    out[row*T_ + tid]       = d0*rs*lng[tid]       + lnb[tid];
    out[row*T_ + tid + 256] = d1*rs*lng[tid + 256] + lnb[tid + 256];
}

extern "C" void kernel_launch(void* const* d_in, const int* in_sizes, int n_in,
                              void* d_out, int out_size){
    const float* residual = (const float*)d_in[0];
    const float* bn_g = (const float*)d_in[1];
    const float* bn_b = (const float*)d_in[2];
    const float* ln_g = (const float*)d_in[3];
    const float* ln_b = (const float*)d_in[4];
    const float* W1   = (const float*)d_in[5];
    const float* b1   = (const float*)d_in[6];
    const float* W2   = (const float*)d_in[7];
    const float* b2   = (const float*)d_in[8];
    float* out = (float*)d_out;

    const int attn_smem = (D_*D_ + D_*TT_) * (int)sizeof(float);   // 86016 B
    cudaFuncSetAttribute(k_attn, cudaFuncAttributeMaxDynamicSharedMemorySize, attn_smem);

    float *px1, *ph, *py;
    cudaGetSymbolAddress((void**)&px1, g_x1);
    cudaGetSymbolAddress((void**)&ph,  g_h);
    cudaGetSymbolAddress((void**)&py,  g_y);

    k_corr<<<B_, 1024>>>(residual);
    dim3 ga(T_/TT_, B_);
    k_attn<<<ga, 512, attn_smem>>>(residual);
    k_bnstats<<<D_, 512>>>(bn_g, bn_b);

    // GEMM1: h = GELU(BN(x1) @ W1 + b1)      [1536 x 1024 x 512]
    dim3 g1(H_/128, BD_/128);
    k_gemm<8, true, true, false><<<g1, 256>>>(px1, W1, b1, nullptr, ph, BD_, H_, T_);
    // GEMM2: y = h @ W2 + b2 + BN(x1)        [1536 x 512 x 1024]
    dim3 g2(T_/64, BD_/128);
    k_gemm<4, false, false, true><<<g2, 256>>>(ph, W2, b2, px1, py, BD_, T_, H_);

    k_ln<<<BD_, 256>>>(ln_g, ln_b, out);
}

// round 5
// speedup vs baseline: 1.7342x; 1.5210x over previous
#include <cuda_runtime.h>
#include <math.h>
#include <stdint.h>

#define B_  16
#define D_  96
#define T_  512
#define H_  1024
#define BD_ (B_*D_)
#define TT_ 128

// ---- scratch ----
__device__ float g_A[B_*D_*D_];
__device__ float g_x1[BD_*T_];
__device__ float g_h[BD_*H_];
__device__ float g_y[BD_*T_];
__device__ float g_bnscale[D_];
__device__ float g_bnoff[D_];

extern __shared__ char dyn_smem[];

__device__ __forceinline__ float warp_sum(float v){
    #pragma unroll
    for(int o=16;o>0;o>>=1) v += __shfl_xor_sync(0xffffffffu, v, o);
    return v;
}
__device__ __forceinline__ float warp_max(float v){
    #pragma unroll
    for(int o=16;o>0;o>>=1) v = fmaxf(v, __shfl_xor_sync(0xffffffffu, v, o));
    return v;
}
__device__ __forceinline__ uint32_t to_tf32(float x){
    uint32_t u; asm("cvt.rna.tf32.f32 %0, %1;" : "=r"(u) : "f"(x));
    return u;
}
__device__ __forceinline__ void mma_tf32(float4& d, const uint32_t a[4], const uint32_t b[2]){
    asm volatile("mma.sync.aligned.m16n8k8.row.col.f32.tf32.tf32.f32 "
        "{%0,%1,%2,%3}, {%4,%5,%6,%7}, {%8,%9}, {%0,%1,%2,%3};"
        : "+f"(d.x), "+f"(d.y), "+f"(d.z), "+f"(d.w)
        : "r"(a[0]), "r"(a[1]), "r"(a[2]), "r"(a[3]), "r"(b[0]), "r"(b[1]));
}

// K1: fused row-sums + rank-1 softmax. grid=B_, block=1024
__global__ void k_corr(const float* __restrict__ res){
    int b = blockIdx.x;
    int tid = threadIdx.x, w = tid >> 5, lane = tid & 31;
    __shared__ float s[D_];
    for (int r = w; r < D_; r += 32){
        const float4* p = (const float4*)(res + (b*D_ + r)*T_);
        float v = 0.f;
        #pragma unroll
        for (int t = lane; t < T_/4; t += 32){
            float4 q = p[t];
            v += (q.x + q.y) + (q.z + q.w);
        }
        v = warp_sum(v);
        if (lane == 0) s[r] = v;
    }
    __syncthreads();
    const float SCALE = 1.0f/11585.237502960395f;   // 1/512^1.5
    for (int r = w; r < D_; r += 32){
        float si = s[r];
        float z0 = si * s[lane     ] * SCALE;
        float z1 = si * s[lane + 32] * SCALE;
        float z2 = si * s[lane + 64] * SCALE;
        float m = warp_max(fmaxf(z0, fmaxf(z1, z2)));
        float e0 = expf(z0 - m), e1 = expf(z1 - m), e2 = expf(z2 - m);
        float inv = 1.f / warp_sum(e0 + e1 + e2);
        float* o = g_A + (b*D_ + r)*D_;
        o[lane]      = e0 * inv;
        o[lane + 32] = e1 * inv;
        o[lane + 64] = e2 * inv;
    }
}

// K2: x1[b,d,t] = sum_e A[b,d,e]*res[b,e,t] + res[b,d,t]
__global__ void k_attn(const float* __restrict__ res){
    float* sm = (float*)dyn_smem;
    float* sA = sm;               // D_*D_  [d][e]
    float* sX = sm + D_*D_;       // D_*TT_ [e][t]
    int b  = blockIdx.y;
    int t0 = blockIdx.x * TT_;
    for (int i = threadIdx.x; i < D_*D_/4; i += 256)
        *(float4*)&sA[i*4] = *(const float4*)&g_A[b*D_*D_ + i*4];
    for (int i = threadIdx.x; i < D_*TT_/4; i += 256){
        int d = (i*4) / TT_, t = (i*4) % TT_;
        *(float4*)&sX[i*4] = *(const float4*)&res[(b*D_+d)*T_ + t0 + t];
    }
    __syncthreads();
    int tx = threadIdx.x & 15;    // 16 t-groups of 8
    int ty = threadIdx.x >> 4;    // 16 d-groups of 6
    int tb = tx*8, db = ty*6;
    float acc[6][8];
    #pragma unroll
    for (int j = 0; j < 6; j++){   // init with residual
        float4 r0 = *(const float4*)&sX[(db+j)*TT_ + tb];
        float4 r1 = *(const float4*)&sX[(db+j)*TT_ + tb + 4];
        acc[j][0]=r0.x; acc[j][1]=r0.y; acc[j][2]=r0.z; acc[j][3]=r0.w;
        acc[j][4]=r1.x; acc[j][5]=r1.y; acc[j][6]=r1.z; acc[j][7]=r1.w;
    }
    #pragma unroll 4
    for (int e = 0; e < D_; e++){
        float4 x0 = *(const float4*)&sX[e*TT_ + tb];
        float4 x1 = *(const float4*)&sX[e*TT_ + tb + 4];
        float xv[8] = {x0.x,x0.y,x0.z,x0.w,x1.x,x1.y,x1.z,x1.w};
        #pragma unroll
        for (int j = 0; j < 6; j++){
            float a = sA[(db+j)*D_ + e];
            #pragma unroll
            for (int i = 0; i < 8; i++)
                acc[j][i] = fmaf(a, xv[i], acc[j][i]);
        }
    }
    #pragma unroll
    for (int j = 0; j < 6; j++){
        float4 v0 = make_float4(acc[j][0],acc[j][1],acc[j][2],acc[j][3]);
        float4 v1 = make_float4(acc[j][4],acc[j][5],acc[j][6],acc[j][7]);
        *(float4*)&g_x1[(b*D_+db+j)*T_ + t0 + tb]     = v0;
        *(float4*)&g_x1[(b*D_+db+j)*T_ + t0 + tb + 4] = v1;
    }
}

// K3: BN stats per channel d over (B,T) -> fused scale/offset
__global__ void k_bnstats(const float* __restrict__ gamma, const float* __restrict__ beta){
    int d = blockIdx.x;
    int tid = threadIdx.x;
    float s = 0.f, ss = 0.f;
    for (int i = tid; i < B_*T_/4; i += 512){
        int b = i >> 7, t4 = i & 127;
        float4 v = *(const float4*)&g_x1[(b*D_+d)*T_ + t4*4];
        s  += (v.x + v.y) + (v.z + v.w);
        ss += (v.x*v.x + v.y*v.y) + (v.z*v.z + v.w*v.w);
    }
    s = warp_sum(s); ss = warp_sum(ss);
    __shared__ float r1[16], r2[16];
    int w = tid >> 5;
    if ((tid & 31) == 0){ r1[w] = s; r2[w] = ss; }
    __syncthreads();
    if (tid == 0){
        float S = 0.f, SS = 0.f;
        #pragma unroll
        for (int k = 0; k < 16; k++){ S += r1[k]; SS += r2[k]; }
        const float invN = 1.f/(float)(B_*T_);
        float mean = S * invN;
        float var  = SS * invN - mean*mean;
        float rs = rsqrtf(var + 1e-5f);
        float sc = rs * gamma[d];
        g_bnscale[d] = sc;
        g_bnoff[d]   = beta[d] - mean * sc;
    }
}

// ======================= tf32 mma.sync GEMM =======================
// C[M,N] = epi( A'[M,K] @ W[K,N] + bias ),  A' = BN(A) if BN_A
// CTA tile 128x64, BK=32, 256 thr (8 warps 4m x 2n), warp tile 32x32.
// Smem (dynamic): A[2][32][136] tf32 + B[2][32][72] tf32.
#define SA_STRIDE 136
#define SB_STRIDE 72
#define SA_BUF    (32*SA_STRIDE)     // 4352 floats
#define SB_BUF    (32*SB_STRIDE)     // 2304 floats
#define GEMM_SMEM ((2*SA_BUF + 2*SB_BUF)*4)   // 53248 B

template<bool GELU, bool BN_A, bool RES_BN>
__global__ void __launch_bounds__(256, 2) k_mma(
    const float* __restrict__ A, const float* __restrict__ Bw,
    const float* __restrict__ bias, const float* __restrict__ ResX,
    float* __restrict__ C, int M, int N, int K)
{
    uint32_t* sm = (uint32_t*)dyn_smem;
    uint32_t* sA = sm;                 // [buf][k][m]
    uint32_t* sB = sm + 2*SA_BUF;      // [buf][k][n]

    int tid = threadIdx.x;
    int w = tid >> 5, lane = tid & 31;
    int tr = lane >> 2, tc = lane & 3;
    int wm = (w & 3) * 32;             // warp m-offset in tile
    int wn = (w >> 2) * 32;            // warp n-offset in tile
    int bn = blockIdx.x * 64, bm = blockIdx.y * 128;

    // ---- staging index precompute ----
    int am[4], ak4[4];                 // A: 4 float4 per thread
    float asc[4], aof[4];
    #pragma unroll
    for (int i = 0; i < 4; i++){
        int idx = tid + i*256;
        am[i] = idx >> 3; ak4[i] = (idx & 7) * 4;
        if (BN_A){ int d = (bm + am[i]) % D_; asc[i] = g_bnscale[d]; aof[i] = g_bnoff[d]; }
    }
    int bk[2], bn4[2];                 // B: 2 float4 per thread
    #pragma unroll
    for (int i = 0; i < 2; i++){
        int idx = tid + i*256;
        bk[i] = idx >> 4; bn4[i] = (idx & 15) * 4;
    }

    float4 acc[2][4];
    #pragma unroll
    for (int i = 0; i < 2; i++)
        #pragma unroll
        for (int j = 0; j < 4; j++) acc[i][j] = make_float4(0.f,0.f,0.f,0.f);

    const int KT = K / 32;

    // prologue: stage tile 0 into buf 0
    #pragma unroll
    for (int i = 0; i < 4; i++){
        float4 v = *(const float4*)&A[(size_t)(bm + am[i])*K + ak4[i]];
        if (BN_A){
            v.x = fmaf(v.x, asc[i], aof[i]); v.y = fmaf(v.y, asc[i], aof[i]);
            v.z = fmaf(v.z, asc[i], aof[i]); v.w = fmaf(v.w, asc[i], aof[i]);
        }
        sA[(ak4[i]+0)*SA_STRIDE + am[i]] = to_tf32(v.x);
        sA[(ak4[i]+1)*SA_STRIDE + am[i]] = to_tf32(v.y);
        sA[(ak4[i]+2)*SA_STRIDE + am[i]] = to_tf32(v.z);
        sA[(ak4[i]+3)*SA_STRIDE + am[i]] = to_tf32(v.w);
    }
    #pragma unroll
    for (int i = 0; i < 2; i++){
        float4 v = *(const float4*)&Bw[(size_t)bk[i]*N + bn + bn4[i]];
        uint4 t = make_uint4(to_tf32(v.x), to_tf32(v.y), to_tf32(v.z), to_tf32(v.w));
        *(uint4*)&sB[bk[i]*SB_STRIDE + bn4[i]] = t;
    }
    __syncthreads();

    for (int kt = 0; kt < KT; kt++){
        int cur = kt & 1;
        const uint32_t* cA = sA + cur*SA_BUF;
        const uint32_t* cB = sB + cur*SB_BUF;
        float4 pa[4]; float4 pb[2];
        bool pf = (kt + 1 < KT);
        if (pf){
            #pragma unroll
            for (int i = 0; i < 4; i++)
                pa[i] = *(const float4*)&A[(size_t)(bm + am[i])*K + (kt+1)*32 + ak4[i]];
            #pragma unroll
            for (int i = 0; i < 2; i++)
                pb[i] = *(const float4*)&Bw[(size_t)(bk[i] + (kt+1)*32)*N + bn + bn4[i]];
        }
        #pragma unroll
        for (int ks = 0; ks < 4; ks++){
            int k0 = ks*8;
            uint32_t af[2][4], bf[4][2];
            #pragma unroll
            for (int i = 0; i < 2; i++){
                int m0 = wm + i*16 + tr;
                af[i][0] = cA[(k0+tc  )*SA_STRIDE + m0];
                af[i][1] = cA[(k0+tc  )*SA_STRIDE + m0 + 8];
                af[i][2] = cA[(k0+tc+4)*SA_STRIDE + m0];
                af[i][3] = cA[(k0+tc+4)*SA_STRIDE + m0 + 8];
            }
            #pragma unroll
            for (int j = 0; j < 4; j++){
                int n0 = wn + j*8 + tr;
                bf[j][0] = cB[(k0+tc  )*SB_STRIDE + n0];
                bf[j][1] = cB[(k0+tc+4)*SB_STRIDE + n0];
            }
            #pragma unroll
            for (int i = 0; i < 2; i++)
                #pragma unroll
                for (int j = 0; j < 4; j++)
                    mma_tf32(acc[i][j], af[i], bf[j]);
        }
        if (pf){
            int nxt = cur ^ 1;
            uint32_t* nA = sA + nxt*SA_BUF;
            uint32_t* nB = sB + nxt*SB_BUF;
            __syncthreads();
            #pragma unroll
            for (int i = 0; i < 4; i++){
                float4 v = pa[i];
                if (BN_A){
                    v.x = fmaf(v.x, asc[i], aof[i]); v.y = fmaf(v.y, asc[i], aof[i]);
                    v.z = fmaf(v.z, asc[i], aof[i]); v.w = fmaf(v.w, asc[i], aof[i]);
                }
                nA[(ak4[i]+0)*SA_STRIDE + am[i]] = to_tf32(v.x);
                nA[(ak4[i]+1)*SA_STRIDE + am[i]] = to_tf32(v.y);
                nA[(ak4[i]+2)*SA_STRIDE + am[i]] = to_tf32(v.z);
                nA[(ak4[i]+3)*SA_STRIDE + am[i]] = to_tf32(v.w);
            }
            #pragma unroll
            for (int i = 0; i < 2; i++){
                uint4 t = make_uint4(to_tf32(pb[i].x), to_tf32(pb[i].y),
                                     to_tf32(pb[i].z), to_tf32(pb[i].w));
                *(uint4*)&nB[bk[i]*SB_STRIDE + bn4[i]] = t;
            }
            __syncthreads();
        }
    }

    // ---- epilogue: bias (+GELU) (+BN residual), direct float2 stores ----
    #pragma unroll
    for (int i = 0; i < 2; i++){
        int r0 = bm + wm + i*16 + tr;
        int r1 = r0 + 8;
        float sc0 = 0.f, of0 = 0.f, sc1 = 0.f, of1 = 0.f;
        if (RES_BN){
            int d0 = r0 % D_, d1 = r1 % D_;
            sc0 = g_bnscale[d0]; of0 = g_bnoff[d0];
            sc1 = g_bnscale[d1]; of1 = g_bnoff[d1];
        }
        #pragma unroll
        for (int j = 0; j < 4; j++){
            int col = bn + wn + j*8 + tc*2;
            float2 bb = *(const float2*)&bias[col];
            float4 v = acc[i][j];
            v.x += bb.x; v.y += bb.y; v.z += bb.x; v.w += bb.y;
            if (GELU){
                v.x = 0.5f*v.x*(1.0f + erff(v.x*0.7071067811865476f));
                v.y = 0.5f*v.y*(1.0f + erff(v.y*0.7071067811865476f));
                v.z = 0.5f*v.z*(1.0f + erff(v.z*0.7071067811865476f));
                v.w = 0.5f*v.w*(1.0f + erff(v.w*0.7071067811865476f));
            }
            if (RES_BN){
                float2 q0 = *(const float2*)&ResX[(size_t)r0*N + col];
                float2 q1 = *(const float2*)&ResX[(size_t)r1*N + col];
                v.x += fmaf(q0.x, sc0, of0); v.y += fmaf(q0.y, sc0, of0);
                v.z += fmaf(q1.x, sc1, of1); v.w += fmaf(q1.y, sc1, of1);
            }
            *(float2*)&C[(size_t)r0*N + col] = make_float2(v.x, v.y);
            *(float2*)&C[(size_t)r1*N + col] = make_float2(v.z, v.w);
        }
    }
}

// K6: LayerNorm over T, write final output
__global__ void k_ln(const float* __restrict__ lng, const float* __restrict__ lnb,
                     float* __restrict__ out){
    int row = blockIdx.x;
    const float* y = g_y + row*T_;
    int tid = threadIdx.x;
    float a = y[tid], b = y[tid + 256];
    __shared__ float red[8];
    int w = tid >> 5;
    float s = warp_sum(a + b);
    if ((tid & 31) == 0) red[w] = s;
    __syncthreads();
    float S = 0.f;
    #pragma unroll
    for (int k = 0; k < 8; k++) S += red[k];
    float mean = S * (1.f/512.f);
    float d0 = a - mean, d1 = b - mean;
    __syncthreads();
    float ss = warp_sum(d0*d0 + d1*d1);
    if ((tid & 31) == 0) red[w] = ss;
    __syncthreads();
    float SS = 0.f;
    #pragma unroll
    for (int k = 0; k < 8; k++) SS += red[k];
    float rs = rsqrtf(SS * (1.f/512.f) + 1e-5f);
    out[row*T_ + tid]       = d0*rs*lng[tid]       + lnb[tid];
    out[row*T_ + tid + 256] = d1*rs*lng[tid + 256] + lnb[tid + 256];
}

extern "C" void kernel_launch(void* const* d_in, const int* in_sizes, int n_in,
                              void* d_out, int out_size){
    const float* residual = (const float*)d_in[0];
    const float* bn_g = (const float*)d_in[1];
    const float* bn_b = (const float*)d_in[2];
    const float* ln_g = (const float*)d_in[3];
    const float* ln_b = (const float*)d_in[4];
    const float* W1   = (const float*)d_in[5];
    const float* b1   = (const float*)d_in[6];
    const float* W2   = (const float*)d_in[7];
    const float* b2   = (const float*)d_in[8];
    float* out = (float*)d_out;

    const int attn_smem = (D_*D_ + D_*TT_) * (int)sizeof(float);   // 86016 B
    cudaFuncSetAttribute(k_attn, cudaFuncAttributeMaxDynamicSharedMemorySize, attn_smem);
    cudaFuncSetAttribute(k_mma<true,  true,  false>, cudaFuncAttributeMaxDynamicSharedMemorySize, GEMM_SMEM);
    cudaFuncSetAttribute(k_mma<false, false, true >, cudaFuncAttributeMaxDynamicSharedMemorySize, GEMM_SMEM);

    float *px1, *ph, *py;
    cudaGetSymbolAddress((void**)&px1, g_x1);
    cudaGetSymbolAddress((void**)&ph,  g_h);
    cudaGetSymbolAddress((void**)&py,  g_y);

    k_corr<<<B_, 1024>>>(residual);
    dim3 ga(T_/TT_, B_);
    k_attn<<<ga, 256, attn_smem>>>(residual);
    k_bnstats<<<D_, 512>>>(bn_g, bn_b);

    // GEMM1: h = GELU(BN(x1) @ W1 + b1)      [1536 x 1024 x 512]
    dim3 g1(H_/64, BD_/128);
    k_mma<true,  true,  false><<<g1, 256, GEMM_SMEM>>>(px1, W1, b1, nullptr, ph, BD_, H_, T_);
    // GEMM2: y = h @ W2 + b2 + BN(x1)        [1536 x 512 x 1024]
    dim3 g2(T_/64, BD_/128);
    k_mma<false, false, true ><<<g2, 256, GEMM_SMEM>>>(ph, W2, b2, px1, py, BD_, T_, H_);

    k_ln<<<BD_, 256>>>(ln_g, ln_b, out);
}

// round 6
// speedup vs baseline: 2.4234x; 1.3974x over previous
#include <cuda_runtime.h>
#include <math.h>
#include <stdint.h>

#define B_  16
#define D_  96
#define T_  512
#define H_  1024
#define BD_ (B_*D_)
#define TT_ 128

// ---- scratch ----
__device__ float g_A[B_*D_*D_];
__device__ float g_x1[BD_*T_];     // attn+res (exact, for BN stats)
__device__ float g_x2r[BD_*T_];    // BN(x1) rounded to tf32 (GEMM1 A + GEMM2 residual)
__device__ float g_h[BD_*H_];      // GELU output, tf32-rounded
__device__ float g_y[BD_*T_];
__device__ float g_w1t[H_*T_];     // W1^T [H][T], tf32-rounded
__device__ float g_w2t[T_*H_];     // W2^T [T][H], tf32-rounded
__device__ float g_bnscale[D_];
__device__ float g_bnoff[D_];

extern __shared__ char dyn_smem[];

__device__ __forceinline__ float warp_sum(float v){
    #pragma unroll
    for(int o=16;o>0;o>>=1) v += __shfl_xor_sync(0xffffffffu, v, o);
    return v;
}
__device__ __forceinline__ float warp_max(float v){
    #pragma unroll
    for(int o=16;o>0;o>>=1) v = fmaxf(v, __shfl_xor_sync(0xffffffffu, v, o));
    return v;
}
__device__ __forceinline__ float to_tf32f(float x){
    uint32_t u; asm("cvt.rna.tf32.f32 %0, %1;" : "=r"(u) : "f"(x));
    return __uint_as_float(u);
}
__device__ __forceinline__ uint32_t smem_u32(const void* p){
    uint32_t a;
    asm("{ .reg .u64 t; cvta.to.shared.u64 t, %1; cvt.u32.u64 %0, t; }" : "=r"(a) : "l"(p));
    return a;
}
__device__ __forceinline__ void mma_tf32(float4& d, const uint32_t a[4], uint32_t b0, uint32_t b1){
    asm volatile("mma.sync.aligned.m16n8k8.row.col.f32.tf32.tf32.f32 "
        "{%0,%1,%2,%3}, {%4,%5,%6,%7}, {%8,%9}, {%0,%1,%2,%3};"
        : "+f"(d.x), "+f"(d.y), "+f"(d.z), "+f"(d.w)
        : "r"(a[0]), "r"(a[1]), "r"(a[2]), "r"(a[3]), "r"(b0), "r"(b1));
}
__device__ __forceinline__ void ldsm_x4(uint32_t* r, uint32_t addr){
    asm volatile("ldmatrix.sync.aligned.m8n8.x4.shared.b16 {%0,%1,%2,%3}, [%4];"
        : "=r"(r[0]), "=r"(r[1]), "=r"(r[2]), "=r"(r[3]) : "r"(addr));
}
__device__ __forceinline__ void cp16(uint32_t dst, const void* src){
    asm volatile("cp.async.ca.shared.global [%0], [%1], 16;" :: "r"(dst), "l"(src));
}
#define CP_COMMIT() asm volatile("cp.async.commit_group;" ::: "memory")
#define CP_WAIT1()  asm volatile("cp.async.wait_group 1;" ::: "memory")
#define CP_WAIT0()  asm volatile("cp.async.wait_group 0;" ::: "memory")

// K0: transpose + round weights to tf32. W[R][C] -> Wt[C][R]
__global__ void k_trans(const float* __restrict__ W, float* __restrict__ Wt, int R, int C){
    __shared__ float tile[32][33];
    int bx = blockIdx.x*32, by = blockIdx.y*32;
    int tx = threadIdx.x, ty = threadIdx.y;
    #pragma unroll
    for (int r = 0; r < 4; r++)
        tile[ty + r*8][tx] = to_tf32f(W[(size_t)(by + ty + r*8)*C + bx + tx]);
    __syncthreads();
    #pragma unroll
    for (int r = 0; r < 4; r++)
        Wt[(size_t)(bx + ty + r*8)*R + by + tx] = tile[tx][ty + r*8];
}

// K1: fused row-sums + rank-1 softmax. grid=B_, block=1024
__global__ void k_corr(const float* __restrict__ res){
    int b = blockIdx.x;
    int tid = threadIdx.x, w = tid >> 5, lane = tid & 31;
    __shared__ float s[D_];
    for (int r = w; r < D_; r += 32){
        const float4* p = (const float4*)(res + (b*D_ + r)*T_);
        float v = 0.f;
        #pragma unroll
        for (int t = lane; t < T_/4; t += 32){
            float4 q = p[t];
            v += (q.x + q.y) + (q.z + q.w);
        }
        v = warp_sum(v);
        if (lane == 0) s[r] = v;
    }
    __syncthreads();
    const float SCALE = 1.0f/11585.237502960395f;   // 1/512^1.5
    for (int r = w; r < D_; r += 32){
        float si = s[r];
        float z0 = si * s[lane     ] * SCALE;
        float z1 = si * s[lane + 32] * SCALE;
        float z2 = si * s[lane + 64] * SCALE;
        float m = warp_max(fmaxf(z0, fmaxf(z1, z2)));
        float e0 = expf(z0 - m), e1 = expf(z1 - m), e2 = expf(z2 - m);
        float inv = 1.f / warp_sum(e0 + e1 + e2);
        float* o = g_A + (b*D_ + r)*D_;
        o[lane]      = e0 * inv;
        o[lane + 32] = e1 * inv;
        o[lane + 64] = e2 * inv;
    }
}

// K2: x1[b,d,t] = sum_e A[b,d,e]*res[b,e,t] + res[b,d,t]
__global__ void k_attn(const float* __restrict__ res){
    float* sm = (float*)dyn_smem;
    float* sA = sm;               // D_*D_  [d][e]
    float* sX = sm + D_*D_;       // D_*TT_ [e][t]
    int b  = blockIdx.y;
    int t0 = blockIdx.x * TT_;
    for (int i = threadIdx.x; i < D_*D_/4; i += 256)
        *(float4*)&sA[i*4] = *(const float4*)&g_A[b*D_*D_ + i*4];
    for (int i = threadIdx.x; i < D_*TT_/4; i += 256){
        int d = (i*4) / TT_, t = (i*4) % TT_;
        *(float4*)&sX[i*4] = *(const float4*)&res[(b*D_+d)*T_ + t0 + t];
    }
    __syncthreads();
    int tx = threadIdx.x & 15;
    int ty = threadIdx.x >> 4;
    int tb = tx*8, db = ty*6;
    float acc[6][8];
    #pragma unroll
    for (int j = 0; j < 6; j++){
        float4 r0 = *(const float4*)&sX[(db+j)*TT_ + tb];
        float4 r1 = *(const float4*)&sX[(db+j)*TT_ + tb + 4];
        acc[j][0]=r0.x; acc[j][1]=r0.y; acc[j][2]=r0.z; acc[j][3]=r0.w;
        acc[j][4]=r1.x; acc[j][5]=r1.y; acc[j][6]=r1.z; acc[j][7]=r1.w;
    }
    #pragma unroll 4
    for (int e = 0; e < D_; e++){
        float4 x0 = *(const float4*)&sX[e*TT_ + tb];
        float4 x1 = *(const float4*)&sX[e*TT_ + tb + 4];
        float xv[8] = {x0.x,x0.y,x0.z,x0.w,x1.x,x1.y,x1.z,x1.w};
        #pragma unroll
        for (int j = 0; j < 6; j++){
            float a = sA[(db+j)*D_ + e];
            #pragma unroll
            for (int i = 0; i < 8; i++)
                acc[j][i] = fmaf(a, xv[i], acc[j][i]);
        }
    }
    #pragma unroll
    for (int j = 0; j < 6; j++){
        float4 v0 = make_float4(acc[j][0],acc[j][1],acc[j][2],acc[j][3]);
        float4 v1 = make_float4(acc[j][4],acc[j][5],acc[j][6],acc[j][7]);
        *(float4*)&g_x1[(b*D_+db+j)*T_ + t0 + tb]     = v0;
        *(float4*)&g_x1[(b*D_+db+j)*T_ + t0 + tb + 4] = v1;
    }
}

// K3: BN stats per channel d over (B,T) -> fused scale/offset
__global__ void k_bnstats(const float* __restrict__ gamma, const float* __restrict__ beta){
    int d = blockIdx.x;
    int tid = threadIdx.x;
    float s = 0.f, ss = 0.f;
    for (int i = tid; i < B_*T_/4; i += 512){
        int b = i >> 7, t4 = i & 127;
        float4 v = *(const float4*)&g_x1[(b*D_+d)*T_ + t4*4];
        s  += (v.x + v.y) + (v.z + v.w);
        ss += (v.x*v.x + v.y*v.y) + (v.z*v.z + v.w*v.w);
    }
    s = warp_sum(s); ss = warp_sum(ss);
    __shared__ float r1[16], r2[16];
    int w = tid >> 5;
    if ((tid & 31) == 0){ r1[w] = s; r2[w] = ss; }
    __syncthreads();
    if (tid == 0){
        float S = 0.f, SS = 0.f;
        #pragma unroll
        for (int k = 0; k < 16; k++){ S += r1[k]; SS += r2[k]; }
        const float invN = 1.f/(float)(B_*T_);
        float mean = S * invN;
        float var  = SS * invN - mean*mean;
        float rs = rsqrtf(var + 1e-5f);
        float sc = rs * gamma[d];
        g_bnscale[d] = sc;
        g_bnoff[d]   = beta[d] - mean * sc;
    }
}

// K4: x2r = tf32( BN(x1) ). grid=BD_, block=128 (one float4/thread)
__global__ void k_bnapply(){
    int row = blockIdx.x, d = row % D_;
    float sc = g_bnscale[d], of = g_bnoff[d];
    int t = threadIdx.x * 4;
    float4 v = *(const float4*)&g_x1[row*T_ + t];
    v.x = to_tf32f(fmaf(v.x, sc, of));
    v.y = to_tf32f(fmaf(v.y, sc, of));
    v.z = to_tf32f(fmaf(v.z, sc, of));
    v.w = to_tf32f(fmaf(v.w, sc, of));
    *(float4*)&g_x2r[row*T_ + t] = v;
}

// ======================= tf32 mma.sync GEMM (ldmatrix + cp.async) =======================
// C[M,N] = epi( A[M,K] @ Bt[N,K]^T + bias [+ Res] )
// CTA 128x64, BK=32, 256 thr (8 warps: 4m x 2n), warp tile 32x32, 3-stage cp.async.
// Smem per stage: A [128][36] + B [64][36] floats (rows padded to 144B).
#define ASTG   18432                 // 128*36*4
#define BSTG   9216                  // 64*36*4
#define STG    (ASTG + BSTG)         // 27648
#define GEMM_SMEM (3*STG)            // 82944

template<bool GELU, bool ROUND, bool RESID>
__global__ void __launch_bounds__(256, 2) k_mma(
    const float* __restrict__ A, const float* __restrict__ Bt,
    const float* __restrict__ bias, const float* __restrict__ Res,
    float* __restrict__ C, int M, int N, int K)
{
    uint32_t sbase = smem_u32(dyn_smem);
    int tid = threadIdx.x, lane = tid & 31, w = tid >> 5;
    int wm = (w & 3) * 32, wn = (w >> 2) * 32;
    int bn = blockIdx.x * 64, bm = blockIdx.y * 128;

    // staging: A 4 x 16B per thread, B 2 x 16B per thread
    uint32_t aSm[4]; const float* aG[4];
    #pragma unroll
    for (int r = 0; r < 4; r++){
        int idx = tid + r*256, m = idx >> 3, kc = idx & 7;
        aSm[r] = (uint32_t)(m*144 + kc*16);
        aG[r]  = A + (size_t)(bm + m)*K + kc*4;
    }
    uint32_t bSm[2]; const float* bG[2];
    #pragma unroll
    for (int r = 0; r < 2; r++){
        int idx = tid + r*256, n = idx >> 3, kc = idx & 7;
        bSm[r] = (uint32_t)(ASTG + n*144 + kc*16);
        bG[r]  = Bt + (size_t)(bn + n)*K + kc*4;
    }

    // ldmatrix fragment offsets (bytes within stage)
    uint32_t aF[2], bF[2];
    {
        int rlo = lane & 7, rmid = (lane >> 3) & 1, khi = lane >> 4;
        aF[0] = (uint32_t)((wm + rlo + 8*rmid)*144 + 16*khi);
        aF[1] = aF[0] + 16*144;
        bF[0] = (uint32_t)(ASTG + (wn + khi*8      + rlo)*144 + 16*rmid);
        bF[1] = (uint32_t)(ASTG + (wn + (2+khi)*8  + rlo)*144 + 16*rmid);
    }

    float4 acc[2][4];
    #pragma unroll
    for (int i = 0; i < 2; i++)
        #pragma unroll
        for (int j = 0; j < 4; j++) acc[i][j] = make_float4(0.f,0.f,0.f,0.f);

    const int KT = K / 32;

    // prologue: stages 0,1
    #pragma unroll
    for (int s = 0; s < 2; s++){
        uint32_t st = sbase + s*STG;
        #pragma unroll
        for (int r = 0; r < 4; r++) cp16(st + aSm[r], aG[r] + s*32);
        #pragma unroll
        for (int r = 0; r < 2; r++) cp16(st + bSm[r], bG[r] + s*32);
        CP_COMMIT();
    }

    int cur = 0, nxtbuf = 2;
    for (int kt = 0; kt < KT; kt++){
        if (kt < KT-1) CP_WAIT1(); else CP_WAIT0();
        __syncthreads();
        if (kt + 2 < KT){
            uint32_t st = sbase + nxtbuf*STG;
            #pragma unroll
            for (int r = 0; r < 4; r++) cp16(st + aSm[r], aG[r] + (kt+2)*32);
            #pragma unroll
            for (int r = 0; r < 2; r++) cp16(st + bSm[r], bG[r] + (kt+2)*32);
            CP_COMMIT();
        }
        uint32_t st = sbase + cur*STG;
        #pragma unroll
        for (int ks = 0; ks < 4; ks++){
            uint32_t a0[4], a1[4], b0[4], b1[4];
            ldsm_x4(a0, st + aF[0] + ks*32);
            ldsm_x4(a1, st + aF[1] + ks*32);
            ldsm_x4(b0, st + bF[0] + ks*32);
            ldsm_x4(b1, st + bF[1] + ks*32);
            mma_tf32(acc[0][0], a0, b0[0], b0[1]);
            mma_tf32(acc[0][1], a0, b0[2], b0[3]);
            mma_tf32(acc[0][2], a0, b1[0], b1[1]);
            mma_tf32(acc[0][3], a0, b1[2], b1[3]);
            mma_tf32(acc[1][0], a1, b0[0], b0[1]);
            mma_tf32(acc[1][1], a1, b0[2], b0[3]);
            mma_tf32(acc[1][2], a1, b1[0], b1[1]);
            mma_tf32(acc[1][3], a1, b1[2], b1[3]);
        }
        cur = (cur + 1 == 3) ? 0 : cur + 1;
        nxtbuf = (nxtbuf + 1 == 3) ? 0 : nxtbuf + 1;
    }

    // epilogue
    int tr = lane >> 2, tc = lane & 3;
    #pragma unroll
    for (int i = 0; i < 2; i++){
        int r0 = bm + wm + i*16 + tr;
        int r1 = r0 + 8;
        #pragma unroll
        for (int j = 0; j < 4; j++){
            int col = bn + wn + j*8 + tc*2;
            float2 bb = *(const float2*)&bias[col];
            float4 v = acc[i][j];
            v.x += bb.x; v.y += bb.y; v.z += bb.x; v.w += bb.y;
            if (GELU){
                v.x = 0.5f*v.x*(1.0f + erff(v.x*0.7071067811865476f));
                v.y = 0.5f*v.y*(1.0f + erff(v.y*0.7071067811865476f));
                v.z = 0.5f*v.z*(1.0f + erff(v.z*0.7071067811865476f));
                v.w = 0.5f*v.w*(1.0f + erff(v.w*0.7071067811865476f));
            }
            if (RESID){
                float2 q0 = *(const float2*)&Res[(size_t)r0*N + col];
                float2 q1 = *(const float2*)&Res[(size_t)r1*N + col];
                v.x += q0.x; v.y += q0.y; v.z += q1.x; v.w += q1.y;
            }
            if (ROUND){
                v.x = to_tf32f(v.x); v.y = to_tf32f(v.y);
                v.z = to_tf32f(v.z); v.w = to_tf32f(v.w);
            }
            *(float2*)&C[(size_t)r0*N + col] = make_float2(v.x, v.y);
            *(float2*)&C[(size_t)r1*N + col] = make_float2(v.z, v.w);
        }
    }
}

// K6: LayerNorm over T, write final output
__global__ void k_ln(const float* __restrict__ lng, const float* __restrict__ lnb,
                     float* __restrict__ out){
    int row = blockIdx.x;
    const float* y = g_y + row*T_;
    int tid = threadIdx.x;
    float a = y[tid], b = y[tid + 256];
    __shared__ float red[8];
    int w = tid >> 5;
    float s = warp_sum(a + b);
    if ((tid & 31) == 0) red[w] = s;
    __syncthreads();
    float S = 0.f;
    #pragma unroll
    for (int k = 0; k < 8; k++) S += red[k];
    float mean = S * (1.f/512.f);
    float d0 = a - mean, d1 = b - mean;
    __syncthreads();
    float ss = warp_sum(d0*d0 + d1*d1);
    if ((tid & 31) == 0) red[w] = ss;
    __syncthreads();
    float SS = 0.f;
    #pragma unroll
    for (int k = 0; k < 8; k++) SS += red[k];
    float rs = rsqrtf(SS * (1.f/512.f) + 1e-5f);
    out[row*T_ + tid]       = d0*rs*lng[tid]       + lnb[tid];
    out[row*T_ + tid + 256] = d1*rs*lng[tid + 256] + lnb[tid + 256];
}

extern "C" void kernel_launch(void* const* d_in, const int* in_sizes, int n_in,
                              void* d_out, int out_size){
    const float* residual = (const float*)d_in[0];
    const float* bn_g = (const float*)d_in[1];
    const float* bn_b = (const float*)d_in[2];
    const float* ln_g = (const float*)d_in[3];
    const float* ln_b = (const float*)d_in[4];
    const float* W1   = (const float*)d_in[5];
    const float* b1   = (const float*)d_in[6];
    const float* W2   = (const float*)d_in[7];
    const float* b2   = (const float*)d_in[8];
    float* out = (float*)d_out;

    const int attn_smem = (D_*D_ + D_*TT_) * (int)sizeof(float);   // 86016 B
    cudaFuncSetAttribute(k_attn, cudaFuncAttributeMaxDynamicSharedMemorySize, attn_smem);
    cudaFuncSetAttribute(k_mma<true,  true,  false>, cudaFuncAttributeMaxDynamicSharedMemorySize, GEMM_SMEM);
    cudaFuncSetAttribute(k_mma<false, false, true >, cudaFuncAttributeMaxDynamicSharedMemorySize, GEMM_SMEM);

    float *px2r, *ph, *py, *pw1t, *pw2t;
    cudaGetSymbolAddress((void**)&px2r, g_x2r);
    cudaGetSymbolAddress((void**)&ph,   g_h);
    cudaGetSymbolAddress((void**)&py,   g_y);
    cudaGetSymbolAddress((void**)&pw1t, g_w1t);
    cudaGetSymbolAddress((void**)&pw2t, g_w2t);

    // weight transposes (independent)
    dim3 tb(32, 8);
    k_trans<<<dim3(H_/32, T_/32), tb>>>(W1, pw1t, T_, H_);   // W1[T][H] -> w1t[H][T]
    k_trans<<<dim3(T_/32, H_/32), tb>>>(W2, pw2t, H_, T_);   // W2[H][T] -> w2t[T][H]

    k_corr<<<B_, 1024>>>(residual);
    dim3 ga(T_/TT_, B_);
    k_attn<<<ga, 256, attn_smem>>>(residual);
    k_bnstats<<<D_, 512>>>(bn_g, bn_b);
    k_bnapply<<<BD_, 128>>>();

    // GEMM1: h = tf32( GELU(x2r @ W1 + b1) )   [1536 x 1024 x 512]
    dim3 g1(H_/64, BD_/128);
    k_mma<true,  true,  false><<<g1, 256, GEMM_SMEM>>>(px2r, pw1t, b1, nullptr, ph, BD_, H_, T_);
    // GEMM2: y = h @ W2 + b2 + x2r             [1536 x 512 x 1024]
    dim3 g2(T_/64, BD_/128);
    k_mma<false, false, true ><<<g2, 256, GEMM_SMEM>>>(ph, pw2t, b2, px2r, py, BD_, T_, H_);

    k_ln<<<BD_, 256>>>(ln_g, ln_b, out);
}

// round 7
// speedup vs baseline: 2.7138x; 1.1198x over previous
#include <cuda_runtime.h>
#include <math.h>
#include <stdint.h>

#define B_  16
#define D_  96
#define T_  512
#define H_  1024
#define BD_ (B_*D_)

// ---- scratch ----
__device__ float g_A[B_*D_*D_];
__device__ float g_x1[BD_*T_];     // attn+res (exact, for BN stats)
__device__ float g_x2r[BD_*T_];    // BN(x1) rounded to tf32 (GEMM1 A + GEMM2 residual)
__device__ float g_h[BD_*H_];      // GELU output, tf32-rounded
__device__ float g_y[BD_*T_];
__device__ float g_w1t[H_*T_];     // W1^T [H][T], tf32-rounded
__device__ float g_w2t[T_*H_];     // W2^T [T][H], tf32-rounded

extern __shared__ char dyn_smem[];

__device__ __forceinline__ float warp_sum(float v){
    #pragma unroll
    for(int o=16;o>0;o>>=1) v += __shfl_xor_sync(0xffffffffu, v, o);
    return v;
}
__device__ __forceinline__ float warp_max(float v){
    #pragma unroll
    for(int o=16;o>0;o>>=1) v = fmaxf(v, __shfl_xor_sync(0xffffffffu, v, o));
    return v;
}
__device__ __forceinline__ float to_tf32f(float x){
    uint32_t u; asm("cvt.rna.tf32.f32 %0, %1;" : "=r"(u) : "f"(x));
    return __uint_as_float(u);
}
__device__ __forceinline__ uint32_t smem_u32(const void* p){
    uint32_t a;
    asm("{ .reg .u64 t; cvta.to.shared.u64 t, %1; cvt.u32.u64 %0, t; }" : "=r"(a) : "l"(p));
    return a;
}
__device__ __forceinline__ void mma_tf32(float4& d, const uint32_t a[4], uint32_t b0, uint32_t b1){
    asm volatile("mma.sync.aligned.m16n8k8.row.col.f32.tf32.tf32.f32 "
        "{%0,%1,%2,%3}, {%4,%5,%6,%7}, {%8,%9}, {%0,%1,%2,%3};"
        : "+f"(d.x), "+f"(d.y), "+f"(d.z), "+f"(d.w)
        : "r"(a[0]), "r"(a[1]), "r"(a[2]), "r"(a[3]), "r"(b0), "r"(b1));
}
__device__ __forceinline__ void ldsm_x4(uint32_t* r, uint32_t addr){
    asm volatile("ldmatrix.sync.aligned.m8n8.x4.shared.b16 {%0,%1,%2,%3}, [%4];"
        : "=r"(r[0]), "=r"(r[1]), "=r"(r[2]), "=r"(r[3]) : "r"(addr));
}
__device__ __forceinline__ void cp16(uint32_t dst, const void* src){
    asm volatile("cp.async.ca.shared.global [%0], [%1], 16;" :: "r"(dst), "l"(src));
}
#define CP_COMMIT() asm volatile("cp.async.commit_group;" ::: "memory")
#define CP_WAIT1()  asm volatile("cp.async.wait_group 1;" ::: "memory")
#define CP_WAIT0()  asm volatile("cp.async.wait_group 0;" ::: "memory")

// K0: transpose + round weights to tf32. W[R][C] -> Wt[C][R]
__global__ void k_trans(const float* __restrict__ W, float* __restrict__ Wt, int R, int C){
    __shared__ float tile[32][33];
    int bx = blockIdx.x*32, by = blockIdx.y*32;
    int tx = threadIdx.x, ty = threadIdx.y;
    #pragma unroll
    for (int r = 0; r < 4; r++)
        tile[ty + r*8][tx] = to_tf32f(W[(size_t)(by + ty + r*8)*C + bx + tx]);
    __syncthreads();
    #pragma unroll
    for (int r = 0; r < 4; r++)
        Wt[(size_t)(bx + ty + r*8)*R + by + tx] = tile[tx][ty + r*8];
}

// K1: fused row-sums + rank-1 softmax. grid=B_, block=1024
__global__ void k_corr(const float* __restrict__ res){
    int b = blockIdx.x;
    int tid = threadIdx.x, w = tid >> 5, lane = tid & 31;
    __shared__ float s[D_];
    for (int r = w; r < D_; r += 32){
        const float4* p = (const float4*)(res + (b*D_ + r)*T_);
        float v = 0.f;
        #pragma unroll
        for (int t = lane; t < T_/4; t += 32){
            float4 q = p[t];
            v += (q.x + q.y) + (q.z + q.w);
        }
        v = warp_sum(v);
        if (lane == 0) s[r] = v;
    }
    __syncthreads();
    const float SCALE = 1.0f/11585.237502960395f;   // 1/512^1.5
    for (int r = w; r < D_; r += 32){
        float si = s[r];
        float z0 = si * s[lane     ] * SCALE;
        float z1 = si * s[lane + 32] * SCALE;
        float z2 = si * s[lane + 64] * SCALE;
        float m = warp_max(fmaxf(z0, fmaxf(z1, z2)));
        float e0 = expf(z0 - m), e1 = expf(z1 - m), e2 = expf(z2 - m);
        float inv = 1.f / warp_sum(e0 + e1 + e2);
        float* o = g_A + (b*D_ + r)*D_;
        o[lane]      = e0 * inv;
        o[lane + 32] = e1 * inv;
        o[lane + 64] = e2 * inv;
    }
}

// K2: x1[b,d,t] = sum_e A[b,d,e]*res[b,e,t] + res[b,d,t]
// grid (T/128, B, 2 d-halves), 256 thr, micro 6d x 4t
__global__ void k_attn(const float* __restrict__ res){
    float* sm = (float*)dyn_smem;
    float* sA = sm;               // 48*96  [dd][e]
    float* sX = sm + 48*D_;       // 96*128 [e][t]
    int b   = blockIdx.y;
    int t0  = blockIdx.x * 128;
    int dh  = blockIdx.z * 48;
    for (int i = threadIdx.x; i < 48*D_/4; i += 256){
        int dd = (i*4) / D_, e = (i*4) % D_;
        *(float4*)&sA[i*4] = *(const float4*)&g_A[(b*D_ + dh + dd)*D_ + e];
    }
    for (int i = threadIdx.x; i < D_*128/4; i += 256){
        int e = (i*4) >> 7, t = (i*4) & 127;
        *(float4*)&sX[i*4] = *(const float4*)&res[(b*D_+e)*T_ + t0 + t];
    }
    __syncthreads();
    int tx = threadIdx.x & 31;    // 32 t-groups of 4
    int ty = threadIdx.x >> 5;    // 8 d-groups of 6
    int tb = tx*4, db = ty*6;
    float acc[6][4];
    #pragma unroll
    for (int j = 0; j < 6; j++){   // init with residual
        float4 r0 = *(const float4*)&sX[(dh+db+j)*128 + tb];
        acc[j][0]=r0.x; acc[j][1]=r0.y; acc[j][2]=r0.z; acc[j][3]=r0.w;
    }
    #pragma unroll 6
    for (int e = 0; e < D_; e++){
        float4 x0 = *(const float4*)&sX[e*128 + tb];
        #pragma unroll
        for (int j = 0; j < 6; j++){
            float a = sA[(db+j)*D_ + e];
            acc[j][0] = fmaf(a, x0.x, acc[j][0]);
            acc[j][1] = fmaf(a, x0.y, acc[j][1]);
            acc[j][2] = fmaf(a, x0.z, acc[j][2]);
            acc[j][3] = fmaf(a, x0.w, acc[j][3]);
        }
    }
    #pragma unroll
    for (int j = 0; j < 6; j++)
        *(float4*)&g_x1[(b*D_ + dh + db + j)*T_ + t0 + tb] =
            make_float4(acc[j][0],acc[j][1],acc[j][2],acc[j][3]);
}

// K3: fused BN stats + apply. grid=D_, 512 thr.
// pass1: mean/var of x1[:,d,:] over (B,T); pass2: x2r = tf32(BN(x1))
__global__ void k_bn(const float* __restrict__ gamma, const float* __restrict__ beta){
    int d = blockIdx.x;
    int tid = threadIdx.x;
    float s = 0.f, ss = 0.f;
    #pragma unroll
    for (int r = 0; r < 4; r++){
        int i = tid + r*512;               // i in [0, 2048): float4 index
        int b = i >> 7, t4 = i & 127;
        float4 v = *(const float4*)&g_x1[(b*D_+d)*T_ + t4*4];
        s  += (v.x + v.y) + (v.z + v.w);
        ss += (v.x*v.x + v.y*v.y) + (v.z*v.z + v.w*v.w);
    }
    s = warp_sum(s); ss = warp_sum(ss);
    __shared__ float r1[16], r2[16];
    __shared__ float bsc, bof;
    int w = tid >> 5;
    if ((tid & 31) == 0){ r1[w] = s; r2[w] = ss; }
    __syncthreads();
    if (tid == 0){
        float S = 0.f, SS = 0.f;
        #pragma unroll
        for (int k = 0; k < 16; k++){ S += r1[k]; SS += r2[k]; }
        const float invN = 1.f/(float)(B_*T_);
        float mean = S * invN;
        float var  = SS * invN - mean*mean;
        float rs = rsqrtf(var + 1e-5f);
        float sc = rs * gamma[d];
        bsc = sc; bof = beta[d] - mean * sc;
    }
    __syncthreads();
    float sc = bsc, of = bof;
    #pragma unroll
    for (int r = 0; r < 4; r++){
        int i = tid + r*512;
        int b = i >> 7, t4 = i & 127;
        float4 v = *(const float4*)&g_x1[(b*D_+d)*T_ + t4*4];
        v.x = to_tf32f(fmaf(v.x, sc, of));
        v.y = to_tf32f(fmaf(v.y, sc, of));
        v.z = to_tf32f(fmaf(v.z, sc, of));
        v.w = to_tf32f(fmaf(v.w, sc, of));
        *(float4*)&g_x2r[(b*D_+d)*T_ + t4*4] = v;
    }
}

// ======================= tf32 mma.sync GEMM (ldmatrix + cp.async) =======================
// C[M,N] = epi( A[M,K] @ Bt[N,K]^T + bias [+ Res] )
// CTA 128x64, BK=32, 256 thr (8 warps: 4m x 2n), warp tile 32x32, 3-stage cp.async.
#define ASTG   18432                 // 128*36*4
#define BSTG   9216                  // 64*36*4
#define STG    (ASTG + BSTG)         // 27648
#define GEMM_SMEM (3*STG)            // 82944

template<bool GELU, bool ROUND, bool RESID>
__global__ void __launch_bounds__(256, 2) k_mma(
    const float* __restrict__ A, const float* __restrict__ Bt,
    const float* __restrict__ bias, const float* __restrict__ Res,
    float* __restrict__ C, int M, int N, int K)
{
    uint32_t sbase = smem_u32(dyn_smem);
    int tid = threadIdx.x, lane = tid & 31, w = tid >> 5;
    int wm = (w & 3) * 32, wn = (w >> 2) * 32;
    int bn = blockIdx.x * 64, bm = blockIdx.y * 128;

    uint32_t aSm[4]; const float* aG[4];
    #pragma unroll
    for (int r = 0; r < 4; r++){
        int idx = tid + r*256, m = idx >> 3, kc = idx & 7;
        aSm[r] = (uint32_t)(m*144 + kc*16);
        aG[r]  = A + (size_t)(bm + m)*K + kc*4;
    }
    uint32_t bSm[2]; const float* bG[2];
    #pragma unroll
    for (int r = 0; r < 2; r++){
        int idx = tid + r*256, n = idx >> 3, kc = idx & 7;
        bSm[r] = (uint32_t)(ASTG + n*144 + kc*16);
        bG[r]  = Bt + (size_t)(bn + n)*K + kc*4;
    }

    uint32_t aF[2], bF[2];
    {
        int rlo = lane & 7, rmid = (lane >> 3) & 1, khi = lane >> 4;
        aF[0] = (uint32_t)((wm + rlo + 8*rmid)*144 + 16*khi);
        aF[1] = aF[0] + 16*144;
        bF[0] = (uint32_t)(ASTG + (wn + khi*8      + rlo)*144 + 16*rmid);
        bF[1] = (uint32_t)(ASTG + (wn + (2+khi)*8  + rlo)*144 + 16*rmid);
    }

    float4 acc[2][4];
    #pragma unroll
    for (int i = 0; i < 2; i++)
        #pragma unroll
        for (int j = 0; j < 4; j++) acc[i][j] = make_float4(0.f,0.f,0.f,0.f);

    const int KT = K / 32;

    #pragma unroll
    for (int s = 0; s < 2; s++){
        uint32_t st = sbase + s*STG;
        #pragma unroll
        for (int r = 0; r < 4; r++) cp16(st + aSm[r], aG[r] + s*32);
        #pragma unroll
        for (int r = 0; r < 2; r++) cp16(st + bSm[r], bG[r] + s*32);
        CP_COMMIT();
    }

    int cur = 0, nxtbuf = 2;
    for (int kt = 0; kt < KT; kt++){
        if (kt < KT-1) CP_WAIT1(); else CP_WAIT0();
        __syncthreads();
        if (kt + 2 < KT){
            uint32_t st = sbase + nxtbuf*STG;
            #pragma unroll
            for (int r = 0; r < 4; r++) cp16(st + aSm[r], aG[r] + (kt+2)*32);
            #pragma unroll
            for (int r = 0; r < 2; r++) cp16(st + bSm[r], bG[r] + (kt+2)*32);
            CP_COMMIT();
        }
        uint32_t st = sbase + cur*STG;
        #pragma unroll
        for (int ks = 0; ks < 4; ks++){
            uint32_t a0[4], a1[4], b0[4], b1[4];
            ldsm_x4(a0, st + aF[0] + ks*32);
            ldsm_x4(a1, st + aF[1] + ks*32);
            ldsm_x4(b0, st + bF[0] + ks*32);
            ldsm_x4(b1, st + bF[1] + ks*32);
            mma_tf32(acc[0][0], a0, b0[0], b0[1]);
            mma_tf32(acc[0][1], a0, b0[2], b0[3]);
            mma_tf32(acc[0][2], a0, b1[0], b1[1]);
            mma_tf32(acc[0][3], a0, b1[2], b1[3]);
            mma_tf32(acc[1][0], a1, b0[0], b0[1]);
            mma_tf32(acc[1][1], a1, b0[2], b0[3]);
            mma_tf32(acc[1][2], a1, b1[0], b1[1]);
            mma_tf32(acc[1][3], a1, b1[2], b1[3]);
        }
        cur = (cur + 1 == 3) ? 0 : cur + 1;
        nxtbuf = (nxtbuf + 1 == 3) ? 0 : nxtbuf + 1;
    }

    int tr = lane >> 2, tc = lane & 3;
    #pragma unroll
    for (int i = 0; i < 2; i++){
        int r0 = bm + wm + i*16 + tr;
        int r1 = r0 + 8;
        #pragma unroll
        for (int j = 0; j < 4; j++){
            int col = bn + wn + j*8 + tc*2;
            float2 bb = *(const float2*)&bias[col];
            float4 v = acc[i][j];
            v.x += bb.x; v.y += bb.y; v.z += bb.x; v.w += bb.y;
            if (GELU){
                v.x = 0.5f*v.x*(1.0f + erff(v.x*0.7071067811865476f));
                v.y = 0.5f*v.y*(1.0f + erff(v.y*0.7071067811865476f));
                v.z = 0.5f*v.z*(1.0f + erff(v.z*0.7071067811865476f));
                v.w = 0.5f*v.w*(1.0f + erff(v.w*0.7071067811865476f));
            }
            if (RESID){
                float2 q0 = *(const float2*)&Res[(size_t)r0*N + col];
                float2 q1 = *(const float2*)&Res[(size_t)r1*N + col];
                v.x += q0.x; v.y += q0.y; v.z += q1.x; v.w += q1.y;
            }
            if (ROUND){
                v.x = to_tf32f(v.x); v.y = to_tf32f(v.y);
                v.z = to_tf32f(v.z); v.w = to_tf32f(v.w);
            }
            *(float2*)&C[(size_t)r0*N + col] = make_float2(v.x, v.y);
            *(float2*)&C[(size_t)r1*N + col] = make_float2(v.z, v.w);
        }
    }
}

// K6: LayerNorm over T, write final output
__global__ void k_ln(const float* __restrict__ lng, const float* __restrict__ lnb,
                     float* __restrict__ out){
    int row = blockIdx.x;
    const float* y = g_y + row*T_;
    int tid = threadIdx.x;
    float a = y[tid], b = y[tid + 256];
    __shared__ float red[8];
    int w = tid >> 5;
    float s = warp_sum(a + b);
    if ((tid & 31) == 0) red[w] = s;
    __syncthreads();
    float S = 0.f;
    #pragma unroll
    for (int k = 0; k < 8; k++) S += red[k];
    float mean = S * (1.f/512.f);
    float d0 = a - mean, d1 = b - mean;
    __syncthreads();
    float ss = warp_sum(d0*d0 + d1*d1);
    if ((tid & 31) == 0) red[w] = ss;
    __syncthreads();
    float SS = 0.f;
    #pragma unroll
    for (int k = 0; k < 8; k++) SS += red[k];
    float rs = rsqrtf(SS * (1.f/512.f) + 1e-5f);
    out[row*T_ + tid]       = d0*rs*lng[tid]       + lnb[tid];
    out[row*T_ + tid + 256] = d1*rs*lng[tid + 256] + lnb[tid + 256];
}

extern "C" void kernel_launch(void* const* d_in, const int* in_sizes, int n_in,
                              void* d_out, int out_size){
    const float* residual = (const float*)d_in[0];
    const float* bn_g = (const float*)d_in[1];
    const float* bn_b = (const float*)d_in[2];
    const float* ln_g = (const float*)d_in[3];
    const float* ln_b = (const float*)d_in[4];
    const float* W1   = (const float*)d_in[5];
    const float* b1   = (const float*)d_in[6];
    const float* W2   = (const float*)d_in[7];
    const float* b2   = (const float*)d_in[8];
    float* out = (float*)d_out;

    const int attn_smem = (48*D_ + D_*128) * (int)sizeof(float);   // 67584 B
    cudaFuncSetAttribute(k_attn, cudaFuncAttributeMaxDynamicSharedMemorySize, attn_smem);
    cudaFuncSetAttribute(k_mma<true,  true,  false>, cudaFuncAttributeMaxDynamicSharedMemorySize, GEMM_SMEM);
    cudaFuncSetAttribute(k_mma<false, false, true >, cudaFuncAttributeMaxDynamicSharedMemorySize, GEMM_SMEM);

    float *px2r, *ph, *py, *pw1t, *pw2t;
    cudaGetSymbolAddress((void**)&px2r, g_x2r);
    cudaGetSymbolAddress((void**)&ph,   g_h);
    cudaGetSymbolAddress((void**)&py,   g_y);
    cudaGetSymbolAddress((void**)&pw1t, g_w1t);
    cudaGetSymbolAddress((void**)&pw2t, g_w2t);

    dim3 tb(32, 8);
    k_trans<<<dim3(H_/32, T_/32), tb>>>(W1, pw1t, T_, H_);   // W1[T][H] -> w1t[H][T]
    k_trans<<<dim3(T_/32, H_/32), tb>>>(W2, pw2t, H_, T_);   // W2[H][T] -> w2t[T][H]

    k_corr<<<B_, 1024>>>(residual);
    dim3 ga(T_/128, B_, 2);
    k_attn<<<ga, 256, attn_smem>>>(residual);
    k_bn<<<D_, 512>>>(bn_g, bn_b);

    // GEMM1: h = tf32( GELU(x2r @ W1 + b1) )   [1536 x 1024 x 512]
    dim3 g1(H_/64, BD_/128);
    k_mma<true,  true,  false><<<g1, 256, GEMM_SMEM>>>(px2r, pw1t, b1, nullptr, ph, BD_, H_, T_);
    // GEMM2: y = h @ W2 + b2 + x2r             [1536 x 512 x 1024]
    dim3 g2(T_/64, BD_/128);
    k_mma<false, false, true ><<<g2, 256, GEMM_SMEM>>>(ph, pw2t, b2, px2r, py, BD_, T_, H_);

    k_ln<<<BD_, 256>>>(ln_g, ln_b, out);
}

// round 8
// speedup vs baseline: 2.7993x; 1.0315x over previous
#include <cuda_runtime.h>
#include <math.h>
#include <stdint.h>

#define B_  16
#define D_  96
#define T_  512
#define H_  1024
#define BD_ (B_*D_)

// ---- scratch ----
__device__ float g_A[B_*D_*D_];
__device__ float g_x1[BD_*T_];     // attn+res (exact, for BN stats)
__device__ float g_x2r[BD_*T_];    // BN(x1) tf32-rounded (GEMM1 A + GEMM2 residual)
__device__ float g_h[BD_*H_];      // GELU output, tf32-rounded
__device__ float g_y[BD_*T_];
__device__ float g_w1t[H_*T_];     // W1^T [H][T], tf32-rounded
__device__ float g_w2t[T_*H_];     // W2^T [T][H], tf32-rounded

extern __shared__ char dyn_smem[];

__device__ __forceinline__ float warp_sum(float v){
    #pragma unroll
    for(int o=16;o>0;o>>=1) v += __shfl_xor_sync(0xffffffffu, v, o);
    return v;
}
__device__ __forceinline__ float warp_max(float v){
    #pragma unroll
    for(int o=16;o>0;o>>=1) v = fmaxf(v, __shfl_xor_sync(0xffffffffu, v, o));
    return v;
}
__device__ __forceinline__ float to_tf32f(float x){
    uint32_t u; asm("cvt.rna.tf32.f32 %0, %1;" : "=r"(u) : "f"(x));
    return __uint_as_float(u);
}
__device__ __forceinline__ uint32_t smem_u32(const void* p){
    uint32_t a;
    asm("{ .reg .u64 t; cvta.to.shared.u64 t, %1; cvt.u32.u64 %0, t; }" : "=r"(a) : "l"(p));
    return a;
}
__device__ __forceinline__ void mma_tf32(float4& d, const uint32_t a[4], uint32_t b0, uint32_t b1){
    asm volatile("mma.sync.aligned.m16n8k8.row.col.f32.tf32.tf32.f32 "
        "{%0,%1,%2,%3}, {%4,%5,%6,%7}, {%8,%9}, {%0,%1,%2,%3};"
        : "+f"(d.x), "+f"(d.y), "+f"(d.z), "+f"(d.w)
        : "r"(a[0]), "r"(a[1]), "r"(a[2]), "r"(a[3]), "r"(b0), "r"(b1));
}
__device__ __forceinline__ void ldsm_x4(uint32_t* r, uint32_t addr){
    asm volatile("ldmatrix.sync.aligned.m8n8.x4.shared.b16 {%0,%1,%2,%3}, [%4];"
        : "=r"(r[0]), "=r"(r[1]), "=r"(r[2]), "=r"(r[3]) : "r"(addr));
}
__device__ __forceinline__ void cp16(uint32_t dst, const void* src){
    asm volatile("cp.async.ca.shared.global [%0], [%1], 16;" :: "r"(dst), "l"(src));
}
#define CP_COMMIT() asm volatile("cp.async.commit_group;" ::: "memory")
#define CP_WAIT1()  asm volatile("cp.async.wait_group 1;" ::: "memory")
#define CP_WAIT0()  asm volatile("cp.async.wait_group 0;" ::: "memory")

// K0: transpose + round BOTH weights in one launch. grid (32,16,2), block (32,8)
__global__ void k_trans2(const float* __restrict__ W1, float* __restrict__ W1t,
                         const float* __restrict__ W2, float* __restrict__ W2t){
    __shared__ float tile[32][33];
    const float* W; float* Wt; int R, C, bx, by;
    if (blockIdx.z == 0){ W = W1; Wt = W1t; R = T_; C = H_;
        bx = blockIdx.x*32; by = blockIdx.y*32; }      // 32 x-blocks over C=1024, 16 y over R=512
    else               { W = W2; Wt = W2t; R = H_; C = T_;
        bx = blockIdx.y*32; by = blockIdx.x*32; }      // 16 col-blocks over C=512, 32 over R=1024
    int tx = threadIdx.x, ty = threadIdx.y;
    #pragma unroll
    for (int r = 0; r < 4; r++)
        tile[ty + r*8][tx] = to_tf32f(W[(size_t)(by + ty + r*8)*C + bx + tx]);
    __syncthreads();
    #pragma unroll
    for (int r = 0; r < 4; r++)
        Wt[(size_t)(bx + ty + r*8)*R + by + tx] = tile[tx][ty + r*8];
}

// K1: fused row-sums + rank-1 softmax. grid=B_, block=1024
__global__ void k_corr(const float* __restrict__ res){
    int b = blockIdx.x;
    int tid = threadIdx.x, w = tid >> 5, lane = tid & 31;
    __shared__ float s[D_];
    for (int r = w; r < D_; r += 32){
        const float4* p = (const float4*)(res + (b*D_ + r)*T_);
        float v = 0.f;
        #pragma unroll
        for (int t = lane; t < T_/4; t += 32){
            float4 q = p[t];
            v += (q.x + q.y) + (q.z + q.w);
        }
        v = warp_sum(v);
        if (lane == 0) s[r] = v;
    }
    __syncthreads();
    const float SCALE = 1.0f/11585.237502960395f;   // 1/512^1.5
    for (int r = w; r < D_; r += 32){
        float si = s[r];
        float z0 = si * s[lane     ] * SCALE;
        float z1 = si * s[lane + 32] * SCALE;
        float z2 = si * s[lane + 64] * SCALE;
        float m = warp_max(fmaxf(z0, fmaxf(z1, z2)));
        float e0 = expf(z0 - m), e1 = expf(z1 - m), e2 = expf(z2 - m);
        float inv = 1.f / warp_sum(e0 + e1 + e2);
        float* o = g_A + (b*D_ + r)*D_;
        o[lane]      = e0 * inv;
        o[lane + 32] = e1 * inv;
        o[lane + 64] = e2 * inv;
    }
}

// K2: x1[b,d,t] = sum_e A[b,d,e]*res[b,e,t] + res[b,d,t]
// grid (T/128, B, 4 d-quarters of 24), 256 thr, micro 3d x 4t, ~58KB smem (3 CTA/SM)
__global__ void k_attn(const float* __restrict__ res){
    float* sm = (float*)dyn_smem;
    float* sA = sm;               // 24*96  [dd][e]
    float* sX = sm + 24*D_;       // 96*128 [e][t]
    int b   = blockIdx.y;
    int t0  = blockIdx.x * 128;
    int dh  = blockIdx.z * 24;
    for (int i = threadIdx.x; i < 24*D_/4; i += 256){
        int dd = (i*4) / D_, e = (i*4) % D_;
        *(float4*)&sA[i*4] = *(const float4*)&g_A[(b*D_ + dh + dd)*D_ + e];
    }
    for (int i = threadIdx.x; i < D_*128/4; i += 256){
        int e = (i*4) >> 7, t = (i*4) & 127;
        *(float4*)&sX[i*4] = *(const float4*)&res[(b*D_+e)*T_ + t0 + t];
    }
    __syncthreads();
    int tx = threadIdx.x & 31;    // 32 t-groups of 4
    int ty = threadIdx.x >> 5;    // 8 d-groups of 3
    int tb = tx*4, db = ty*3;
    float acc[3][4];
    #pragma unroll
    for (int j = 0; j < 3; j++){   // init with residual
        float4 r0 = *(const float4*)&sX[(dh+db+j)*128 + tb];
        acc[j][0]=r0.x; acc[j][1]=r0.y; acc[j][2]=r0.z; acc[j][3]=r0.w;
    }
    #pragma unroll 8
    for (int e = 0; e < D_; e++){
        float4 x0 = *(const float4*)&sX[e*128 + tb];
        #pragma unroll
        for (int j = 0; j < 3; j++){
            float a = sA[(db+j)*D_ + e];
            acc[j][0] = fmaf(a, x0.x, acc[j][0]);
            acc[j][1] = fmaf(a, x0.y, acc[j][1]);
            acc[j][2] = fmaf(a, x0.z, acc[j][2]);
            acc[j][3] = fmaf(a, x0.w, acc[j][3]);
        }
    }
    #pragma unroll
    for (int j = 0; j < 3; j++)
        *(float4*)&g_x1[(b*D_ + dh + db + j)*T_ + t0 + tb] =
            make_float4(acc[j][0],acc[j][1],acc[j][2],acc[j][3]);
}

// K3: fused BN stats + apply. grid=D_, 512 thr.
__global__ void k_bn(const float* __restrict__ gamma, const float* __restrict__ beta){
    int d = blockIdx.x;
    int tid = threadIdx.x;
    float s = 0.f, ss = 0.f;
    #pragma unroll
    for (int r = 0; r < 4; r++){
        int i = tid + r*512;
        int b = i >> 7, t4 = i & 127;
        float4 v = *(const float4*)&g_x1[(b*D_+d)*T_ + t4*4];
        s  += (v.x + v.y) + (v.z + v.w);
        ss += (v.x*v.x + v.y*v.y) + (v.z*v.z + v.w*v.w);
    }
    s = warp_sum(s); ss = warp_sum(ss);
    __shared__ float r1[16], r2[16];
    __shared__ float bsc, bof;
    int w = tid >> 5;
    if ((tid & 31) == 0){ r1[w] = s; r2[w] = ss; }
    __syncthreads();
    if (tid == 0){
        float S = 0.f, SS = 0.f;
        #pragma unroll
        for (int k = 0; k < 16; k++){ S += r1[k]; SS += r2[k]; }
        const float invN = 1.f/(float)(B_*T_);
        float mean = S * invN;
        float var  = SS * invN - mean*mean;
        float rs = rsqrtf(var + 1e-5f);
        float sc = rs * gamma[d];
        bsc = sc; bof = beta[d] - mean * sc;
    }
    __syncthreads();
    float sc = bsc, of = bof;
    #pragma unroll
    for (int r = 0; r < 4; r++){
        int i = tid + r*512;
        int b = i >> 7, t4 = i & 127;
        float4 v = *(const float4*)&g_x1[(b*D_+d)*T_ + t4*4];
        v.x = to_tf32f(fmaf(v.x, sc, of));
        v.y = to_tf32f(fmaf(v.y, sc, of));
        v.z = to_tf32f(fmaf(v.z, sc, of));
        v.w = to_tf32f(fmaf(v.w, sc, of));
        *(float4*)&g_x2r[(b*D_+d)*T_ + t4*4] = v;
    }
}

// ======================= tf32 mma.sync GEMM (ldmatrix + cp.async) =======================
// C[M,N] = epi( A[M,K] @ Bt[N,K]^T + bias [+ Res] )
// CTA tile 128 x (NW*32), BK=32, 256 thr (8 warps: 4m x 2n), warp tile 32 x (NW*16).
#define ASTG 18432   // 128*36*4

template<int NW, bool GELU, bool ROUND, bool RESID>
__global__ void __launch_bounds__(256, 1) k_mma(
    const float* __restrict__ A, const float* __restrict__ Bt,
    const float* __restrict__ bias, const float* __restrict__ Res,
    float* __restrict__ C, int M, int N, int K)
{
    constexpr int BNT  = NW*32;          // block N tile
    constexpr int BSTG = BNT*144;
    constexpr int STG  = ASTG + BSTG;
    constexpr int NB4  = BNT/32;         // B float4 loads per thread

    uint32_t sbase = smem_u32(dyn_smem);
    int tid = threadIdx.x, lane = tid & 31, w = tid >> 5;
    int wm = (w & 3) * 32, wn = (w >> 2) * (NW*16);
    int bn = blockIdx.x * BNT, bm = blockIdx.y * 128;

    uint32_t aSm[4]; const float* aG[4];
    #pragma unroll
    for (int r = 0; r < 4; r++){
        int idx = tid + r*256, m = idx >> 3, kc = idx & 7;
        aSm[r] = (uint32_t)(m*144 + kc*16);
        aG[r]  = A + (size_t)(bm + m)*K + kc*4;
    }
    uint32_t bSm[NB4]; const float* bG[NB4];
    #pragma unroll
    for (int r = 0; r < NB4; r++){
        int idx = tid + r*256, n = idx >> 3, kc = idx & 7;
        bSm[r] = (uint32_t)(ASTG + n*144 + kc*16);
        bG[r]  = Bt + (size_t)(bn + n)*K + kc*4;
    }

    uint32_t aF[2], bF[NW];
    {
        int rlo = lane & 7, rmid = (lane >> 3) & 1, khi = lane >> 4;
        aF[0] = (uint32_t)((wm + rlo + 8*rmid)*144 + 16*khi);
        aF[1] = aF[0] + 16*144;
        #pragma unroll
        for (int j = 0; j < NW; j++)
            bF[j] = (uint32_t)(ASTG + (wn + j*16 + khi*8 + rlo)*144 + 16*rmid);
    }

    float4 acc[2][2*NW];
    #pragma unroll
    for (int i = 0; i < 2; i++)
        #pragma unroll
        for (int j = 0; j < 2*NW; j++) acc[i][j] = make_float4(0.f,0.f,0.f,0.f);

    const int KT = K / 32;

    #pragma unroll
    for (int s = 0; s < 2; s++){
        uint32_t st = sbase + s*STG;
        #pragma unroll
        for (int r = 0; r < 4; r++) cp16(st + aSm[r], aG[r] + s*32);
        #pragma unroll
        for (int r = 0; r < NB4; r++) cp16(st + bSm[r], bG[r] + s*32);
        CP_COMMIT();
    }

    int cur = 0, nxtbuf = 2;
    for (int kt = 0; kt < KT; kt++){
        if (kt < KT-1) CP_WAIT1(); else CP_WAIT0();
        __syncthreads();
        if (kt + 2 < KT){
            uint32_t st = sbase + nxtbuf*STG;
            #pragma unroll
            for (int r = 0; r < 4; r++) cp16(st + aSm[r], aG[r] + (kt+2)*32);
            #pragma unroll
            for (int r = 0; r < NB4; r++) cp16(st + bSm[r], bG[r] + (kt+2)*32);
            CP_COMMIT();
        }
        uint32_t st = sbase + cur*STG;
        #pragma unroll
        for (int ks = 0; ks < 4; ks++){
            uint32_t a0[4], a1[4], bfr[NW][4];
            ldsm_x4(a0, st + aF[0] + ks*32);
            ldsm_x4(a1, st + aF[1] + ks*32);
            #pragma unroll
            for (int j = 0; j < NW; j++) ldsm_x4(bfr[j], st + bF[j] + ks*32);
            #pragma unroll
            for (int j = 0; j < NW; j++){
                mma_tf32(acc[0][2*j  ], a0, bfr[j][0], bfr[j][1]);
                mma_tf32(acc[0][2*j+1], a0, bfr[j][2], bfr[j][3]);
                mma_tf32(acc[1][2*j  ], a1, bfr[j][0], bfr[j][1]);
                mma_tf32(acc[1][2*j+1], a1, bfr[j][2], bfr[j][3]);
            }
        }
        cur = (cur + 1 == 3) ? 0 : cur + 1;
        nxtbuf = (nxtbuf + 1 == 3) ? 0 : nxtbuf + 1;
    }

    int tr = lane >> 2, tc = lane & 3;
    #pragma unroll
    for (int i = 0; i < 2; i++){
        int r0 = bm + wm + i*16 + tr;
        int r1 = r0 + 8;
        #pragma unroll
        for (int j = 0; j < 2*NW; j++){
            int col = bn + wn + j*8 + tc*2;
            float2 bb = *(const float2*)&bias[col];
            float4 v = acc[i][j];
            v.x += bb.x; v.y += bb.y; v.z += bb.x; v.w += bb.y;
            if (GELU){
                v.x = 0.5f*v.x*(1.0f + erff(v.x*0.7071067811865476f));
                v.y = 0.5f*v.y*(1.0f + erff(v.y*0.7071067811865476f));
                v.z = 0.5f*v.z*(1.0f + erff(v.z*0.7071067811865476f));
                v.w = 0.5f*v.w*(1.0f + erff(v.w*0.7071067811865476f));
            }
            if (RESID){
                float2 q0 = *(const float2*)&Res[(size_t)r0*N + col];
                float2 q1 = *(const float2*)&Res[(size_t)r1*N + col];
                v.x += q0.x; v.y += q0.y; v.z += q1.x; v.w += q1.y;
            }
            if (ROUND){
                v.x = to_tf32f(v.x); v.y = to_tf32f(v.y);
                v.z = to_tf32f(v.z); v.w = to_tf32f(v.w);
            }
            *(float2*)&C[(size_t)r0*N + col] = make_float2(v.x, v.y);
            *(float2*)&C[(size_t)r1*N + col] = make_float2(v.z, v.w);
        }
    }
}

// K6: LayerNorm over T, write final output
__global__ void k_ln(const float* __restrict__ lng, const float* __restrict__ lnb,
                     float* __restrict__ out){
    int row = blockIdx.x;
    const float* y = g_y + row*T_;
    int tid = threadIdx.x;
    float a = y[tid], b = y[tid + 256];
    __shared__ float red[8];
    int w = tid >> 5;
    float s = warp_sum(a + b);
    if ((tid & 31) == 0) red[w] = s;
    __syncthreads();
    float S = 0.f;
    #pragma unroll
    for (int k = 0; k < 8; k++) S += red[k];
    float mean = S * (1.f/512.f);
    float d0 = a - mean, d1 = b - mean;
    __syncthreads();
    float ss = warp_sum(d0*d0 + d1*d1);
    if ((tid & 31) == 0) red[w] = ss;
    __syncthreads();
    float SS = 0.f;
    #pragma unroll
    for (int k = 0; k < 8; k++) SS += red[k];
    float rs = rsqrtf(SS * (1.f/512.f) + 1e-5f);
    out[row*T_ + tid]       = d0*rs*lng[tid]       + lnb[tid];
    out[row*T_ + tid + 256] = d1*rs*lng[tid + 256] + lnb[tid + 256];
}

extern "C" void kernel_launch(void* const* d_in, const int* in_sizes, int n_in,
                              void* d_out, int out_size){
    const float* residual = (const float*)d_in[0];
    const float* bn_g = (const float*)d_in[1];
    const float* bn_b = (const float*)d_in[2];
    const float* ln_g = (const float*)d_in[3];
    const float* ln_b = (const float*)d_in[4];
    const float* W1   = (const float*)d_in[5];
    const float* b1   = (const float*)d_in[6];
    const float* W2   = (const float*)d_in[7];
    const float* b2   = (const float*)d_in[8];
    float* out = (float*)d_out;

    const int attn_smem = (24*D_ + D_*128) * (int)sizeof(float);   // 58368 B
    const int g1_smem = 3*(ASTG + 128*144);                        // 110592 B
    const int g2_smem = 3*(ASTG + 64*144);                         // 82944 B
    cudaFuncSetAttribute(k_attn, cudaFuncAttributeMaxDynamicSharedMemorySize, attn_smem);
    cudaFuncSetAttribute(k_mma<4, true,  true,  false>, cudaFuncAttributeMaxDynamicSharedMemorySize, g1_smem);
    cudaFuncSetAttribute(k_mma<2, false, false, true >, cudaFuncAttributeMaxDynamicSharedMemorySize, g2_smem);

    float *px2r, *ph, *py, *pw1t, *pw2t;
    cudaGetSymbolAddress((void**)&px2r, g_x2r);
    cudaGetSymbolAddress((void**)&ph,   g_h);
    cudaGetSymbolAddress((void**)&py,   g_y);
    cudaGetSymbolAddress((void**)&pw1t, g_w1t);
    cudaGetSymbolAddress((void**)&pw2t, g_w2t);

    k_trans2<<<dim3(32,16,2), dim3(32,8)>>>(W1, pw1t, W2, pw2t);

    k_corr<<<B_, 1024>>>(residual);
    dim3 ga(T_/128, B_, 4);
    k_attn<<<ga, 256, attn_smem>>>(residual);
    k_bn<<<D_, 512>>>(bn_g, bn_b);

    // GEMM1: h = tf32( GELU(x2r @ W1 + b1) )   [1536 x 1024 x 512], 128x128 tiles
    dim3 g1(H_/128, BD_/128);
    k_mma<4, true,  true,  false><<<g1, 256, g1_smem>>>(px2r, pw1t, b1, nullptr, ph, BD_, H_, T_);
    // GEMM2: y = h @ W2 + b2 + x2r             [1536 x 512 x 1024], 128x64 tiles
    dim3 g2(T_/64, BD_/128);
    k_mma<2, false, false, true ><<<g2, 256, g2_smem>>>(ph, pw2t, b2, px2r, py, BD_, T_, H_);

    k_ln<<<BD_, 256>>>(ln_g, ln_b, out);
}